// round 4
// baseline (speedup 1.0000x reference)
#include <cuda_runtime.h>
#include <math.h>
#include <stdint.h>

// Problem constants
#define B_   4
#define E_   32
#define D_   1024
#define NH_  16
#define NP_  4
#define LQ_  1024          // E*E
#define DH_  64            // D/NH

// ---------------------------------------------------------------------------
// Scratch (static device globals; allocation APIs are forbidden)
// ---------------------------------------------------------------------------
__device__ float g_fn   [B_ * 4 * LQ_ * D_];   // 64 MB  LN(concat srcs), tf32
__device__ float g_qn   [B_ * LQ_ * D_];       // 16 MB  LN(src3), tf32
__device__ float g_val  [B_ * 4 * LQ_ * D_];   // 64 MB  CA value
__device__ float g_off  [B_ * LQ_ * 512];      //  8 MB
__device__ float g_aw   [B_ * LQ_ * 256];      //  4 MB
__device__ float g_samp [B_ * LQ_ * D_];       // 16 MB  CA sampled, tf32
__device__ float g_attn [B_ * LQ_ * D_];       // 16 MB
__device__ float g_attn1[B_ * LQ_ * D_];       // 16 MB  LN(attn), tf32
__device__ float g_val2 [B_ * LQ_ * D_];       // 16 MB
__device__ float g_off2 [B_ * LQ_ * 128];      //  2 MB
__device__ float g_aw2  [B_ * LQ_ * 64];       //  1 MB
__device__ float g_samp2[B_ * LQ_ * D_];       // 16 MB  tf32
__device__ float g_attn2[B_ * LQ_ * D_];       // 16 MB
__device__ float g_wr   [5177344];             // 20.7 MB tf32-rounded weights

// Weight segment offsets (floats) inside g_wr
#define WOFF_CAVW 0
#define WOFF_CAOW 1048576
#define WOFF_CAAW 1572864
#define WOFF_CAPW 1835008
#define WOFF_SAVW 2883584
#define WOFF_SAOW 3932160
#define WOFF_SAAW 4063232
#define WOFF_SAPW 4128768
#define WTOT      5177344

// ---------------------------------------------------------------------------
// Helpers
// ---------------------------------------------------------------------------
__device__ __forceinline__ uint32_t smem_u32(const void* p) {
    uint32_t a;
    asm("{ .reg .u64 t; cvta.to.shared.u64 t, %1; cvt.u32.u64 %0, t; }"
        : "=r"(a) : "l"(p));
    return a;
}
__device__ __forceinline__ void cp16(uint32_t s, const void* g) {
    asm volatile("cp.async.cg.shared.global [%0], [%1], 16;\n" :: "r"(s), "l"(g));
}
__device__ __forceinline__ void cp16p(uint32_t s, const void* g, uint32_t nbytes) {
    asm volatile("cp.async.cg.shared.global [%0], [%1], 16, %2;\n"
                 :: "r"(s), "l"(g), "r"(nbytes));
}
__device__ __forceinline__ float rnd_tf32(float f) {
    uint32_t o;
    asm("cvt.rna.tf32.f32 %0, %1;" : "=r"(o) : "f"(f));
    return __uint_as_float(o);
}
__device__ __forceinline__ void mma_tf32(float* d, const uint32_t* a, const uint32_t* b) {
    asm volatile(
        "mma.sync.aligned.m16n8k8.row.col.f32.tf32.tf32.f32 "
        "{%0,%1,%2,%3}, {%4,%5,%6,%7}, {%8,%9}, {%0,%1,%2,%3};"
        : "+f"(d[0]), "+f"(d[1]), "+f"(d[2]), "+f"(d[3])
        : "r"(a[0]), "r"(a[1]), "r"(a[2]), "r"(a[3]), "r"(b[0]), "r"(b[1]));
}

// ---------------------------------------------------------------------------
// TF32 tensor-core GEMM:  C(M,N) = A(M,K=1024) @ W(N,K=1024)^T + bias(N)
// Block 128x128x32, 4 warps (64x64 each), 3-stage cp.async pipeline.
// Inputs A/W must be pre-rounded to tf32 (raw bits fed to mma).
// k-permutation: within a BK=32 stage, thread quad-lane c owns smem k-positions
// [8c, 8c+8); MMA step i consumes positions {8c+2i, 8c+2i+1} -> LDS.64 frags.
// ---------------------------------------------------------------------------
#define LDSS 36          // smem row stride in floats (32 + 4 pad)
#define STG  (128*LDSS)  // floats per matrix per stage
#define NSTAGE 3

__global__ void __launch_bounds__(128) gemm_tf32(
    const float* __restrict__ A, const float* __restrict__ W,
    const float* __restrict__ bias, float* __restrict__ C, int N)
{
    extern __shared__ float sm[];
    float* Asm = sm;
    float* Bsm = sm + NSTAGE * STG;

    const int K = 1024, NIT = 32;
    int tid = threadIdx.x, wid = tid >> 5, lane = tid & 31;
    int wm = wid & 1, wn = wid >> 1;
    int g = lane >> 2, c = lane & 3;
    int bm = blockIdx.y * 128, bn = blockIdx.x * 128;

    uint32_t abase = smem_u32(Asm), bbase = smem_u32(Bsm);

    float acc[4][8][4];
    #pragma unroll
    for (int mt = 0; mt < 4; mt++)
        #pragma unroll
        for (int nt = 0; nt < 8; nt++)
            #pragma unroll
            for (int i = 0; i < 4; i++) acc[mt][nt][i] = 0.f;

    int rowA = tid >> 3, jA = tid & 7;

    auto load_stage = [&](int s, int it) {
        int k0 = it * 32;
        #pragma unroll
        for (int i = 0; i < 8; ++i) {
            int row = rowA + i * 16;
            cp16(abase + (uint32_t)(s * STG + row * LDSS + jA * 4) * 4,
                 A + (size_t)(bm + row) * K + k0 + jA * 4);
        }
        #pragma unroll
        for (int i = 0; i < 8; ++i) {
            int row = rowA + i * 16;
            int srow = bn + row;
            const float* src = W + (size_t)(srow < N ? srow : 0) * K + k0 + jA * 4;
            cp16p(bbase + (uint32_t)(s * STG + row * LDSS + jA * 4) * 4,
                  src, srow < N ? 16u : 0u);
        }
        asm volatile("cp.async.commit_group;" ::: "memory");
    };

    load_stage(0, 0);
    load_stage(1, 1);

    for (int it = 0; it < NIT; ++it) {
        int s = it % NSTAGE;
        asm volatile("cp.async.wait_group 1;" ::: "memory");
        __syncthreads();
        if (it + 2 < NIT) load_stage((it + 2) % NSTAGE, it + 2);

        const float* Ab = Asm + s * STG;
        const float* Bb = Bsm + s * STG;
        int kc = 8 * c;
        #pragma unroll
        for (int ks = 0; ks < 4; ks++) {
            uint32_t af[4][4], bf[8][2];
            int col = kc + 2 * ks;
            #pragma unroll
            for (int mt = 0; mt < 4; mt++) {
                int r = wm * 64 + mt * 16 + g;
                float2 a0 = *(const float2*)&Ab[r * LDSS + col];
                float2 a1 = *(const float2*)&Ab[(r + 8) * LDSS + col];
                af[mt][0] = __float_as_uint(a0.x);
                af[mt][1] = __float_as_uint(a1.x);
                af[mt][2] = __float_as_uint(a0.y);
                af[mt][3] = __float_as_uint(a1.y);
            }
            #pragma unroll
            for (int nt = 0; nt < 8; nt++) {
                int r = wn * 64 + nt * 8 + g;
                float2 b = *(const float2*)&Bb[r * LDSS + col];
                bf[nt][0] = __float_as_uint(b.x);
                bf[nt][1] = __float_as_uint(b.y);
            }
            #pragma unroll
            for (int mt = 0; mt < 4; mt++)
                #pragma unroll
                for (int nt = 0; nt < 8; nt++)
                    mma_tf32(acc[mt][nt], af[mt], bf[nt]);
        }
    }

    // Epilogue
    #pragma unroll
    for (int mt = 0; mt < 4; mt++) {
        int r0 = bm + wm * 64 + mt * 16 + g;
        #pragma unroll
        for (int nt = 0; nt < 8; nt++) {
            int colb = bn + wn * 64 + nt * 8;
            if (colb < N) {
                int cg = colb + 2 * c;
                float2 bv = *(const float2*)(bias + cg);
                float2 o0 = { acc[mt][nt][0] + bv.x, acc[mt][nt][1] + bv.y };
                float2 o1 = { acc[mt][nt][2] + bv.x, acc[mt][nt][3] + bv.y };
                *(float2*)(C + (size_t)r0 * N + cg) = o0;
                *(float2*)(C + (size_t)(r0 + 8) * N + cg) = o1;
            }
        }
    }
}

// ---------------------------------------------------------------------------
// LayerNorm (one block per 1024-float row). RND: round output to tf32.
// ---------------------------------------------------------------------------
template<bool RND>
__global__ void __launch_bounds__(256) ln_kernel(
    const float* __restrict__ in, const float* __restrict__ g,
    const float* __restrict__ b, float* __restrict__ out,
    int in_rpb, int out_rpb, int out_off)
{
    __shared__ float red[16];
    int r = blockIdx.x;
    int bb = r / in_rpb;
    int rr = r - bb * in_rpb;
    const float4* x4 = (const float4*)(in + (size_t)r * D_);
    float4* y4 = (float4*)(out + ((size_t)bb * out_rpb + out_off + rr) * D_);

    int t = threadIdx.x;
    float4 v = x4[t];
    float s  = v.x + v.y + v.z + v.w;
    float ss = v.x * v.x + v.y * v.y + v.z * v.z + v.w * v.w;
    #pragma unroll
    for (int o = 16; o; o >>= 1) {
        s  += __shfl_xor_sync(0xFFFFFFFFu, s,  o);
        ss += __shfl_xor_sync(0xFFFFFFFFu, ss, o);
    }
    int warp = t >> 5, lane = t & 31;
    if (lane == 0) { red[warp] = s; red[8 + warp] = ss; }
    __syncthreads();
    if (t == 0) {
        float S = 0.f, SS = 0.f;
        #pragma unroll
        for (int i = 0; i < 8; i++) { S += red[i]; SS += red[8 + i]; }
        red[0] = S; red[8] = SS;
    }
    __syncthreads();
    float mean = red[0] * (1.0f / D_);
    float var  = red[8] * (1.0f / D_) - mean * mean;
    float inv  = rsqrtf(var + 1e-6f);

    float4 gg = ((const float4*)g)[t];
    float4 bv = ((const float4*)b)[t];
    float4 o;
    o.x = (v.x - mean) * inv * gg.x + bv.x;
    o.y = (v.y - mean) * inv * gg.y + bv.y;
    o.z = (v.z - mean) * inv * gg.z + bv.z;
    o.w = (v.w - mean) * inv * gg.w + bv.w;
    if (RND) {
        o.x = rnd_tf32(o.x); o.y = rnd_tf32(o.y);
        o.z = rnd_tf32(o.z); o.w = rnd_tf32(o.w);
    }
    y4[t] = o;
}

// Fused feat-LN: 4 srcs -> concat layout, tf32-rounded. grid = 16384.
__global__ void __launch_bounds__(256) ln_feat_kernel(
    const float* __restrict__ s0, const float* __restrict__ s1,
    const float* __restrict__ s2, const float* __restrict__ s3,
    const float* __restrict__ g, const float* __restrict__ b,
    float* __restrict__ out)
{
    __shared__ float red[16];
    int l = blockIdx.x >> 12;
    int r = blockIdx.x & 4095;
    const float* in = (l == 0) ? s0 : (l == 1) ? s1 : (l == 2) ? s2 : s3;
    int bb = r >> 10, rr = r & 1023;
    const float4* x4 = (const float4*)(in + (size_t)r * D_);
    float4* y4 = (float4*)(out + ((size_t)bb * 4096 + l * 1024 + rr) * D_);

    int t = threadIdx.x;
    float4 v = x4[t];
    float s  = v.x + v.y + v.z + v.w;
    float ss = v.x * v.x + v.y * v.y + v.z * v.z + v.w * v.w;
    #pragma unroll
    for (int o = 16; o; o >>= 1) {
        s  += __shfl_xor_sync(0xFFFFFFFFu, s,  o);
        ss += __shfl_xor_sync(0xFFFFFFFFu, ss, o);
    }
    int warp = t >> 5, lane = t & 31;
    if (lane == 0) { red[warp] = s; red[8 + warp] = ss; }
    __syncthreads();
    if (t == 0) {
        float S = 0.f, SS = 0.f;
        #pragma unroll
        for (int i = 0; i < 8; i++) { S += red[i]; SS += red[8 + i]; }
        red[0] = S; red[8] = SS;
    }
    __syncthreads();
    float mean = red[0] * (1.0f / D_);
    float var  = red[8] * (1.0f / D_) - mean * mean;
    float inv  = rsqrtf(var + 1e-6f);

    float4 gg = ((const float4*)g)[t];
    float4 bv = ((const float4*)b)[t];
    float4 o;
    o.x = rnd_tf32((v.x - mean) * inv * gg.x + bv.x);
    o.y = rnd_tf32((v.y - mean) * inv * gg.y + bv.y);
    o.z = rnd_tf32((v.z - mean) * inv * gg.z + bv.z);
    o.w = rnd_tf32((v.w - mean) * inv * gg.w + bv.w);
    y4[t] = o;
}

// ---------------------------------------------------------------------------
// Round all 8 weight matrices to tf32 into g_wr (single launch).
// ---------------------------------------------------------------------------
struct WPtrs { const float4 *p0,*p1,*p2,*p3,*p4,*p5,*p6,*p7; };

__global__ void round_weights(WPtrs w, float4* __restrict__ dst)
{
    int i = blockIdx.x * blockDim.x + threadIdx.x;   // float4 index
    if (i >= WTOT / 4) return;
    const float4* src; int base;
    if      (i < WOFF_CAOW/4) { src = w.p0; base = 0; }
    else if (i < WOFF_CAAW/4) { src = w.p1; base = WOFF_CAOW/4; }
    else if (i < WOFF_CAPW/4) { src = w.p2; base = WOFF_CAAW/4; }
    else if (i < WOFF_SAVW/4) { src = w.p3; base = WOFF_CAPW/4; }
    else if (i < WOFF_SAOW/4) { src = w.p4; base = WOFF_SAVW/4; }
    else if (i < WOFF_SAAW/4) { src = w.p5; base = WOFF_SAOW/4; }
    else if (i < WOFF_SAPW/4) { src = w.p6; base = WOFF_SAAW/4; }
    else                      { src = w.p7; base = WOFF_SAPW/4; }
    float4 v = src[i - base];
    v.x = rnd_tf32(v.x); v.y = rnd_tf32(v.y);
    v.z = rnd_tf32(v.z); v.w = rnd_tf32(v.w);
    dst[i] = v;
}

// ---------------------------------------------------------------------------
// Softmax over P contiguous entries per (b,q,h).
// ---------------------------------------------------------------------------
__global__ void softmax_kernel(float* __restrict__ aw, int P, int total)
{
    int i = blockIdx.x * blockDim.x + threadIdx.x;
    if (i >= total) return;
    float* p = aw + (size_t)i * P;
    float m = -1e30f;
    for (int j = 0; j < P; j++) m = fmaxf(m, p[j]);
    float s = 0.f;
    for (int j = 0; j < P; j++) { float e = __expf(p[j] - m); p[j] = e; s += e; }
    float inv = 1.0f / s;
    for (int j = 0; j < P; j++) p[j] *= inv;
}

// ---------------------------------------------------------------------------
// Deformable sampling: 1 block per (b,q), 16 warps = heads, float2 per lane.
// Output rounded to tf32 (feeds the projection GEMM).
// ---------------------------------------------------------------------------
template<int NL>
__global__ void __launch_bounds__(512) deform_sample(
    const float* __restrict__ value, const float* __restrict__ off,
    const float* __restrict__ attw, float* __restrict__ out)
{
    int bq = blockIdx.x;
    int b = bq >> 10, q = bq & 1023;
    int h = threadIdx.x >> 5, lane = threadIdx.x & 31;

    float rx = ((q & 31) + 0.5f) * 0.03125f;
    float ry = ((q >> 5) + 0.5f) * 0.03125f;

    const float* offp = off  + ((size_t)bq * NH_ + h) * (NL * NP_ * 2);
    const float* awp  = attw + ((size_t)bq * NH_ + h) * (NL * NP_);
    const float* vbase = value + (size_t)b * (NL * 1024) * D_ + h * DH_;

    float2 acc = make_float2(0.f, 0.f);

    #pragma unroll
    for (int l = 0; l < NL; l++) {
        #pragma unroll
        for (int p = 0; p < NP_; p++) {
            int s = l * NP_ + p;
            float ox = offp[s * 2 + 0];
            float oy = offp[s * 2 + 1];
            float a  = awp[s];
            float x = (rx + ox * 0.03125f) * 32.0f - 0.5f;
            float y = (ry + oy * 0.03125f) * 32.0f - 0.5f;
            float x0f = floorf(x), y0f = floorf(y);
            float wx1 = x - x0f, wy1 = y - y0f;
            int x0 = (int)x0f, y0 = (int)y0f;
            #pragma unroll
            for (int dy = 0; dy < 2; dy++) {
                int yi = y0 + dy;
                if ((unsigned)yi >= 32u) continue;
                float wy = dy ? wy1 : (1.0f - wy1);
                #pragma unroll
                for (int dx = 0; dx < 2; dx++) {
                    int xi = x0 + dx;
                    if ((unsigned)xi >= 32u) continue;
                    float w = (dx ? wx1 : (1.0f - wx1)) * wy * a;
                    const float2* vp = (const float2*)(vbase +
                        ((size_t)l * 1024 + yi * 32 + xi) * D_);
                    float2 v = vp[lane];
                    acc.x += v.x * w;
                    acc.y += v.y * w;
                }
            }
        }
    }
    float2 o = { rnd_tf32(acc.x), rnd_tf32(acc.y) };
    ((float2*)(out + (size_t)bq * D_ + h * DH_))[lane] = o;
}

// ---------------------------------------------------------------------------
// Final residual combine: out = src3 + g1*(attn + g2*attn2)
// ---------------------------------------------------------------------------
__global__ void final_kernel(
    const float* __restrict__ src3, const float* __restrict__ attn,
    const float* __restrict__ attn2, const float* __restrict__ g1,
    const float* __restrict__ g2, float* __restrict__ out, int n4)
{
    int i = blockIdx.x * blockDim.x + threadIdx.x;
    if (i >= n4) return;
    int d4 = i & (D_ / 4 - 1);
    float4 s = ((const float4*)src3)[i];
    float4 a = ((const float4*)attn)[i];
    float4 a2 = ((const float4*)attn2)[i];
    float4 G1 = ((const float4*)g1)[d4];
    float4 G2 = ((const float4*)g2)[d4];
    float4 o;
    o.x = s.x + G1.x * (a.x + G2.x * a2.x);
    o.y = s.y + G1.y * (a.y + G2.y * a2.y);
    o.z = s.z + G1.z * (a.z + G2.z * a2.z);
    o.w = s.w + G1.w * (a.w + G2.w * a2.w);
    ((float4*)out)[i] = o;
}

// ---------------------------------------------------------------------------
// Host launcher
// ---------------------------------------------------------------------------
extern "C" void kernel_launch(void* const* d_in, const int* in_sizes, int n_in,
                              void* d_out, int out_size)
{
    const float* src[4] = {(const float*)d_in[0], (const float*)d_in[1],
                           (const float*)d_in[2], (const float*)d_in[3]};
    const float* qn_g = (const float*)d_in[4];
    const float* qn_b = (const float*)d_in[5];
    const float* fn_g = (const float*)d_in[6];
    const float* fn_b = (const float*)d_in[7];
    const float* n1_g = (const float*)d_in[8];
    const float* n1_b = (const float*)d_in[9];
    const float* gamma1 = (const float*)d_in[10];
    const float* gamma2 = (const float*)d_in[11];
    const float* ca_vb = (const float*)d_in[13];
    const float* ca_ob = (const float*)d_in[15];
    const float* ca_ab = (const float*)d_in[17];
    const float* ca_pb = (const float*)d_in[19];
    const float* sa_vb = (const float*)d_in[21];
    const float* sa_ob = (const float*)d_in[23];
    const float* sa_ab = (const float*)d_in[25];
    const float* sa_pb = (const float*)d_in[27];

    float *fn, *qn, *val, *off, *aw, *samp, *attn, *attn1;
    float *val2, *off2, *aw2, *samp2, *attn2, *wr;
    cudaGetSymbolAddress((void**)&fn,    g_fn);
    cudaGetSymbolAddress((void**)&qn,    g_qn);
    cudaGetSymbolAddress((void**)&val,   g_val);
    cudaGetSymbolAddress((void**)&off,   g_off);
    cudaGetSymbolAddress((void**)&aw,    g_aw);
    cudaGetSymbolAddress((void**)&samp,  g_samp);
    cudaGetSymbolAddress((void**)&attn,  g_attn);
    cudaGetSymbolAddress((void**)&attn1, g_attn1);
    cudaGetSymbolAddress((void**)&val2,  g_val2);
    cudaGetSymbolAddress((void**)&off2,  g_off2);
    cudaGetSymbolAddress((void**)&aw2,   g_aw2);
    cudaGetSymbolAddress((void**)&samp2, g_samp2);
    cudaGetSymbolAddress((void**)&attn2, g_attn2);
    cudaGetSymbolAddress((void**)&wr,    g_wr);

    const int ROWS = B_ * LQ_;                    // 4096
    const int SMEM = 2 * NSTAGE * STG * 4;        // 110592 bytes

    cudaFuncSetAttribute(gemm_tf32, cudaFuncAttributeMaxDynamicSharedMemorySize, SMEM);

    WPtrs wp = { (const float4*)d_in[12], (const float4*)d_in[14],
                 (const float4*)d_in[16], (const float4*)d_in[18],
                 (const float4*)d_in[20], (const float4*)d_in[22],
                 (const float4*)d_in[24], (const float4*)d_in[26] };

    // Launch order arranged so ncu (-s 5 -c 1) captures launch #6 = CA value GEMM.
    // 1-2) LayerNorms (tf32-rounded outputs)
    ln_feat_kernel<<<4 * ROWS, 256>>>(src[0], src[1], src[2], src[3], fn_g, fn_b, fn);
    ln_kernel<true><<<ROWS, 256>>>(src[3], qn_g, qn_b, qn, LQ_, LQ_, 0);
    // 3) Round weights to tf32
    round_weights<<<(WTOT / 4 + 255) / 256, 256>>>(wp, (float4*)wr);
    // 4-6) CA GEMMs (off, aw, value)
    gemm_tf32<<<dim3(4, 32),  128, SMEM>>>(qn, wr + WOFF_CAOW, ca_ob, off, 512);
    gemm_tf32<<<dim3(2, 32),  128, SMEM>>>(qn, wr + WOFF_CAAW, ca_ab, aw,  256);
    gemm_tf32<<<dim3(8, 128), 128, SMEM>>>(fn, wr + WOFF_CAVW, ca_vb, val, 1024);
    // 7-9) softmax, sample, project
    softmax_kernel<<<(ROWS * NH_ + 255) / 256, 256>>>(aw, 16, ROWS * NH_);
    deform_sample<4><<<ROWS, 512>>>(val, off, aw, samp);
    gemm_tf32<<<dim3(8, 32),  128, SMEM>>>(samp, wr + WOFF_CAPW, ca_pb, attn, 1024);
    // 10-16) SA branch
    ln_kernel<true><<<ROWS, 256>>>(attn, n1_g, n1_b, attn1, LQ_, LQ_, 0);
    gemm_tf32<<<dim3(8, 32),  128, SMEM>>>(attn1, wr + WOFF_SAVW, sa_vb, val2, 1024);
    gemm_tf32<<<dim3(1, 32),  128, SMEM>>>(attn1, wr + WOFF_SAOW, sa_ob, off2, 128);
    gemm_tf32<<<dim3(1, 32),  128, SMEM>>>(attn1, wr + WOFF_SAAW, sa_ab, aw2,  64);
    softmax_kernel<<<(ROWS * NH_ + 255) / 256, 256>>>(aw2, 4, ROWS * NH_);
    deform_sample<1><<<ROWS, 512>>>(val2, off2, aw2, samp2);
    gemm_tf32<<<dim3(8, 32),  128, SMEM>>>(samp2, wr + WOFF_SAPW, sa_pb, attn2, 1024);
    // 17) Final combine
    final_kernel<<<(ROWS * D_ / 4 + 255) / 256, 256>>>(
        src[3], attn, attn2, gamma1, gamma2, (float*)d_out, ROWS * D_ / 4);
}

// round 5
// speedup vs baseline: 1.4017x; 1.4017x over previous
#include <cuda_runtime.h>
#include <math.h>
#include <stdint.h>

// Problem constants
#define B_   4
#define E_   32
#define D_   1024
#define NH_  16
#define NP_  4
#define LQ_  1024          // E*E
#define DH_  64            // D/NH

// ---------------------------------------------------------------------------
// Scratch (static device globals; allocation APIs are forbidden)
// ---------------------------------------------------------------------------
__device__ float g_fn   [B_ * 4 * LQ_ * D_];   // 64 MB  LN(concat srcs), tf32
__device__ float g_qn   [B_ * LQ_ * D_];       // 16 MB  LN(src3), tf32
__device__ float g_val  [B_ * 4 * LQ_ * D_];   // 64 MB  CA value
__device__ float g_off  [B_ * LQ_ * 512];      //  8 MB
__device__ float g_aw   [B_ * LQ_ * 256];      //  4 MB
__device__ float g_samp [B_ * LQ_ * D_];       // 16 MB  CA sampled, tf32
__device__ float g_attn [B_ * LQ_ * D_];       // 16 MB
__device__ float g_attn1[B_ * LQ_ * D_];       // 16 MB  LN(attn), tf32
__device__ float g_val2 [B_ * LQ_ * D_];       // 16 MB
__device__ float g_off2 [B_ * LQ_ * 128];      //  2 MB
__device__ float g_aw2  [B_ * LQ_ * 64];       //  1 MB
__device__ float g_samp2[B_ * LQ_ * D_];       // 16 MB  tf32
__device__ float g_attn2[B_ * LQ_ * D_];       // 16 MB
__device__ float g_wr   [5177344];             // 20.7 MB tf32-rounded weights

// Weight segment offsets (floats) inside g_wr
#define WOFF_CAVW 0
#define WOFF_CAOW 1048576
#define WOFF_CAAW 1572864
#define WOFF_CAPW 1835008
#define WOFF_SAVW 2883584
#define WOFF_SAOW 3932160
#define WOFF_SAAW 4063232
#define WOFF_SAPW 4128768
#define WTOT      5177344

// ---------------------------------------------------------------------------
// Helpers
// ---------------------------------------------------------------------------
__device__ __forceinline__ uint32_t smem_u32(const void* p) {
    uint32_t a;
    asm("{ .reg .u64 t; cvta.to.shared.u64 t, %1; cvt.u32.u64 %0, t; }"
        : "=r"(a) : "l"(p));
    return a;
}
__device__ __forceinline__ void cp16(uint32_t s, const void* g) {
    asm volatile("cp.async.cg.shared.global [%0], [%1], 16;\n" :: "r"(s), "l"(g));
}
__device__ __forceinline__ void cp16p(uint32_t s, const void* g, uint32_t nbytes) {
    asm volatile("cp.async.cg.shared.global [%0], [%1], 16, %2;\n"
                 :: "r"(s), "l"(g), "r"(nbytes));
}
__device__ __forceinline__ float rnd_tf32(float f) {
    uint32_t o;
    asm("cvt.rna.tf32.f32 %0, %1;" : "=r"(o) : "f"(f));
    return __uint_as_float(o);
}
__device__ __forceinline__ void mma_tf32(float* d, const uint32_t* a, const uint32_t* b) {
    asm volatile(
        "mma.sync.aligned.m16n8k8.row.col.f32.tf32.tf32.f32 "
        "{%0,%1,%2,%3}, {%4,%5,%6,%7}, {%8,%9}, {%0,%1,%2,%3};"
        : "+f"(d[0]), "+f"(d[1]), "+f"(d[2]), "+f"(d[3])
        : "r"(a[0]), "r"(a[1]), "r"(a[2]), "r"(a[3]), "r"(b[0]), "r"(b[1]));
}

// ---------------------------------------------------------------------------
// TF32 tensor-core GEMM:  C(M,N) = A(M,K=1024) @ W(N,K=1024)^T + bias(N)
// Block 128x128x32, 256 threads / 8 warps (each warp 32x64), 3-stage cp.async.
// Inputs A/W pre-rounded to tf32 (raw bits fed to mma, no in-loop cvt).
// k-permutation: quad-lane c owns smem k-positions [8c, 8c+8); MMA step i
// consumes {8c+2i, 8c+2i+1} -> all fragment loads are conflict-light LDS.64.
// Valid because A and B use the same k-bijection within each BK=32 stage.
// ---------------------------------------------------------------------------
#define LDSS 36          // smem row stride in floats (32 + 4 pad)
#define STG  (128*LDSS)  // floats per matrix per stage
#define NSTAGE 3

__global__ void __launch_bounds__(256) gemm_tf32(
    const float* __restrict__ A, const float* __restrict__ W,
    const float* __restrict__ bias, float* __restrict__ C, int N)
{
    extern __shared__ float sm[];
    float* Asm = sm;
    float* Bsm = sm + NSTAGE * STG;

    const int K = 1024, NIT = 32;
    int tid = threadIdx.x, wid = tid >> 5, lane = tid & 31;
    int wm = wid & 3, wn = wid >> 2;          // warp tile: rows wm*32, cols wn*64
    int g = lane >> 2, c = lane & 3;
    int bm = blockIdx.y * 128, bn = blockIdx.x * 128;

    uint32_t abase = smem_u32(Asm), bbase = smem_u32(Bsm);

    float acc[2][8][4];
    #pragma unroll
    for (int mt = 0; mt < 2; mt++)
        #pragma unroll
        for (int nt = 0; nt < 8; nt++)
            #pragma unroll
            for (int i = 0; i < 4; i++) acc[mt][nt][i] = 0.f;

    int rowA = tid >> 3, jA = tid & 7;   // 256 threads: 32 rows x 8 chunks / pass

    auto load_stage = [&](int s, int it) {
        int k0 = it * 32;
        #pragma unroll
        for (int i = 0; i < 4; ++i) {
            int row = rowA + i * 32;
            cp16(abase + (uint32_t)(s * STG + row * LDSS + jA * 4) * 4,
                 A + (size_t)(bm + row) * K + k0 + jA * 4);
        }
        #pragma unroll
        for (int i = 0; i < 4; ++i) {
            int row = rowA + i * 32;
            int srow = bn + row;
            const float* src = W + (size_t)(srow < N ? srow : 0) * K + k0 + jA * 4;
            cp16p(bbase + (uint32_t)(s * STG + row * LDSS + jA * 4) * 4,
                  src, srow < N ? 16u : 0u);
        }
        asm volatile("cp.async.commit_group;" ::: "memory");
    };

    load_stage(0, 0);
    load_stage(1, 1);

    int s = 0, pf = 2;   // compute stage, prefetch stage (wrap counters, no %)
    for (int it = 0; it < NIT; ++it) {
        asm volatile("cp.async.wait_group 1;" ::: "memory");
        __syncthreads();
        if (it + 2 < NIT) {
            load_stage(pf, it + 2);
            pf = (pf == NSTAGE - 1) ? 0 : pf + 1;
        }

        const float* Ab = Asm + s * STG;
        const float* Bb = Bsm + s * STG;
        int kc = 8 * c;
        #pragma unroll
        for (int ks = 0; ks < 4; ks++) {
            uint32_t af[2][4], bf[8][2];
            int col = kc + 2 * ks;
            #pragma unroll
            for (int mt = 0; mt < 2; mt++) {
                int r = wm * 32 + mt * 16 + g;
                float2 a0 = *(const float2*)&Ab[r * LDSS + col];
                float2 a1 = *(const float2*)&Ab[(r + 8) * LDSS + col];
                af[mt][0] = __float_as_uint(a0.x);
                af[mt][1] = __float_as_uint(a1.x);
                af[mt][2] = __float_as_uint(a0.y);
                af[mt][3] = __float_as_uint(a1.y);
            }
            #pragma unroll
            for (int nt = 0; nt < 8; nt++) {
                int r = wn * 64 + nt * 8 + g;
                float2 b = *(const float2*)&Bb[r * LDSS + col];
                bf[nt][0] = __float_as_uint(b.x);
                bf[nt][1] = __float_as_uint(b.y);
            }
            #pragma unroll
            for (int mt = 0; mt < 2; mt++)
                #pragma unroll
                for (int nt = 0; nt < 8; nt++)
                    mma_tf32(acc[mt][nt], af[mt], bf[nt]);
        }
        s = (s == NSTAGE - 1) ? 0 : s + 1;
    }

    // Epilogue
    #pragma unroll
    for (int mt = 0; mt < 2; mt++) {
        int r0 = bm + wm * 32 + mt * 16 + g;
        #pragma unroll
        for (int nt = 0; nt < 8; nt++) {
            int colb = bn + wn * 64 + nt * 8;
            if (colb < N) {
                int cg = colb + 2 * c;
                float2 bv = *(const float2*)(bias + cg);
                float2 o0 = { acc[mt][nt][0] + bv.x, acc[mt][nt][1] + bv.y };
                float2 o1 = { acc[mt][nt][2] + bv.x, acc[mt][nt][3] + bv.y };
                *(float2*)(C + (size_t)r0 * N + cg) = o0;
                *(float2*)(C + (size_t)(r0 + 8) * N + cg) = o1;
            }
        }
    }
}

// ---------------------------------------------------------------------------
// LayerNorm (one block per 1024-float row). RND: round output to tf32.
// ---------------------------------------------------------------------------
template<bool RND>
__global__ void __launch_bounds__(256) ln_kernel(
    const float* __restrict__ in, const float* __restrict__ g,
    const float* __restrict__ b, float* __restrict__ out,
    int in_rpb, int out_rpb, int out_off)
{
    __shared__ float red[16];
    int r = blockIdx.x;
    int bb = r / in_rpb;
    int rr = r - bb * in_rpb;
    const float4* x4 = (const float4*)(in + (size_t)r * D_);
    float4* y4 = (float4*)(out + ((size_t)bb * out_rpb + out_off + rr) * D_);

    int t = threadIdx.x;
    float4 v = x4[t];
    float s  = v.x + v.y + v.z + v.w;
    float ss = v.x * v.x + v.y * v.y + v.z * v.z + v.w * v.w;
    #pragma unroll
    for (int o = 16; o; o >>= 1) {
        s  += __shfl_xor_sync(0xFFFFFFFFu, s,  o);
        ss += __shfl_xor_sync(0xFFFFFFFFu, ss, o);
    }
    int warp = t >> 5, lane = t & 31;
    if (lane == 0) { red[warp] = s; red[8 + warp] = ss; }
    __syncthreads();
    if (t == 0) {
        float S = 0.f, SS = 0.f;
        #pragma unroll
        for (int i = 0; i < 8; i++) { S += red[i]; SS += red[8 + i]; }
        red[0] = S; red[8] = SS;
    }
    __syncthreads();
    float mean = red[0] * (1.0f / D_);
    float var  = red[8] * (1.0f / D_) - mean * mean;
    float inv  = rsqrtf(var + 1e-6f);

    float4 gg = ((const float4*)g)[t];
    float4 bv = ((const float4*)b)[t];
    float4 o;
    o.x = (v.x - mean) * inv * gg.x + bv.x;
    o.y = (v.y - mean) * inv * gg.y + bv.y;
    o.z = (v.z - mean) * inv * gg.z + bv.z;
    o.w = (v.w - mean) * inv * gg.w + bv.w;
    if (RND) {
        o.x = rnd_tf32(o.x); o.y = rnd_tf32(o.y);
        o.z = rnd_tf32(o.z); o.w = rnd_tf32(o.w);
    }
    y4[t] = o;
}

// Fused feat-LN: 4 srcs -> concat layout, tf32-rounded. grid = 16384.
__global__ void __launch_bounds__(256) ln_feat_kernel(
    const float* __restrict__ s0, const float* __restrict__ s1,
    const float* __restrict__ s2, const float* __restrict__ s3,
    const float* __restrict__ g, const float* __restrict__ b,
    float* __restrict__ out)
{
    __shared__ float red[16];
    int l = blockIdx.x >> 12;
    int r = blockIdx.x & 4095;
    const float* in = (l == 0) ? s0 : (l == 1) ? s1 : (l == 2) ? s2 : s3;
    int bb = r >> 10, rr = r & 1023;
    const float4* x4 = (const float4*)(in + (size_t)r * D_);
    float4* y4 = (float4*)(out + ((size_t)bb * 4096 + l * 1024 + rr) * D_);

    int t = threadIdx.x;
    float4 v = x4[t];
    float s  = v.x + v.y + v.z + v.w;
    float ss = v.x * v.x + v.y * v.y + v.z * v.z + v.w * v.w;
    #pragma unroll
    for (int o = 16; o; o >>= 1) {
        s  += __shfl_xor_sync(0xFFFFFFFFu, s,  o);
        ss += __shfl_xor_sync(0xFFFFFFFFu, ss, o);
    }
    int warp = t >> 5, lane = t & 31;
    if (lane == 0) { red[warp] = s; red[8 + warp] = ss; }
    __syncthreads();
    if (t == 0) {
        float S = 0.f, SS = 0.f;
        #pragma unroll
        for (int i = 0; i < 8; i++) { S += red[i]; SS += red[8 + i]; }
        red[0] = S; red[8] = SS;
    }
    __syncthreads();
    float mean = red[0] * (1.0f / D_);
    float var  = red[8] * (1.0f / D_) - mean * mean;
    float inv  = rsqrtf(var + 1e-6f);

    float4 gg = ((const float4*)g)[t];
    float4 bv = ((const float4*)b)[t];
    float4 o;
    o.x = rnd_tf32((v.x - mean) * inv * gg.x + bv.x);
    o.y = rnd_tf32((v.y - mean) * inv * gg.y + bv.y);
    o.z = rnd_tf32((v.z - mean) * inv * gg.z + bv.z);
    o.w = rnd_tf32((v.w - mean) * inv * gg.w + bv.w);
    y4[t] = o;
}

// ---------------------------------------------------------------------------
// Round all 8 weight matrices to tf32 into g_wr (single launch).
// ---------------------------------------------------------------------------
struct WPtrs { const float4 *p0,*p1,*p2,*p3,*p4,*p5,*p6,*p7; };

__global__ void round_weights(WPtrs w, float4* __restrict__ dst)
{
    int i = blockIdx.x * blockDim.x + threadIdx.x;   // float4 index
    if (i >= WTOT / 4) return;
    const float4* src; int base;
    if      (i < WOFF_CAOW/4) { src = w.p0; base = 0; }
    else if (i < WOFF_CAAW/4) { src = w.p1; base = WOFF_CAOW/4; }
    else if (i < WOFF_CAPW/4) { src = w.p2; base = WOFF_CAAW/4; }
    else if (i < WOFF_SAVW/4) { src = w.p3; base = WOFF_CAPW/4; }
    else if (i < WOFF_SAOW/4) { src = w.p4; base = WOFF_SAVW/4; }
    else if (i < WOFF_SAAW/4) { src = w.p5; base = WOFF_SAOW/4; }
    else if (i < WOFF_SAPW/4) { src = w.p6; base = WOFF_SAAW/4; }
    else                      { src = w.p7; base = WOFF_SAPW/4; }
    float4 v = src[i - base];
    v.x = rnd_tf32(v.x); v.y = rnd_tf32(v.y);
    v.z = rnd_tf32(v.z); v.w = rnd_tf32(v.w);
    dst[i] = v;
}

// ---------------------------------------------------------------------------
// Softmax over P contiguous entries per (b,q,h).
// ---------------------------------------------------------------------------
__global__ void softmax_kernel(float* __restrict__ aw, int P, int total)
{
    int i = blockIdx.x * blockDim.x + threadIdx.x;
    if (i >= total) return;
    float* p = aw + (size_t)i * P;
    float m = -1e30f;
    for (int j = 0; j < P; j++) m = fmaxf(m, p[j]);
    float s = 0.f;
    for (int j = 0; j < P; j++) { float e = __expf(p[j] - m); p[j] = e; s += e; }
    float inv = 1.0f / s;
    for (int j = 0; j < P; j++) p[j] *= inv;
}

// ---------------------------------------------------------------------------
// Deformable sampling: 1 block per (b,q), 16 warps = heads, float2 per lane.
// Output rounded to tf32 (feeds the projection GEMM).
// ---------------------------------------------------------------------------
template<int NL>
__global__ void __launch_bounds__(512) deform_sample(
    const float* __restrict__ value, const float* __restrict__ off,
    const float* __restrict__ attw, float* __restrict__ out)
{
    int bq = blockIdx.x;
    int b = bq >> 10, q = bq & 1023;
    int h = threadIdx.x >> 5, lane = threadIdx.x & 31;

    float rx = ((q & 31) + 0.5f) * 0.03125f;
    float ry = ((q >> 5) + 0.5f) * 0.03125f;

    const float* offp = off  + ((size_t)bq * NH_ + h) * (NL * NP_ * 2);
    const float* awp  = attw + ((size_t)bq * NH_ + h) * (NL * NP_);
    const float* vbase = value + (size_t)b * (NL * 1024) * D_ + h * DH_;

    float2 acc = make_float2(0.f, 0.f);

    #pragma unroll
    for (int l = 0; l < NL; l++) {
        #pragma unroll
        for (int p = 0; p < NP_; p++) {
            int s = l * NP_ + p;
            float ox = offp[s * 2 + 0];
            float oy = offp[s * 2 + 1];
            float a  = awp[s];
            float x = (rx + ox * 0.03125f) * 32.0f - 0.5f;
            float y = (ry + oy * 0.03125f) * 32.0f - 0.5f;
            float x0f = floorf(x), y0f = floorf(y);
            float wx1 = x - x0f, wy1 = y - y0f;
            int x0 = (int)x0f, y0 = (int)y0f;
            #pragma unroll
            for (int dy = 0; dy < 2; dy++) {
                int yi = y0 + dy;
                if ((unsigned)yi >= 32u) continue;
                float wy = dy ? wy1 : (1.0f - wy1);
                #pragma unroll
                for (int dx = 0; dx < 2; dx++) {
                    int xi = x0 + dx;
                    if ((unsigned)xi >= 32u) continue;
                    float w = (dx ? wx1 : (1.0f - wx1)) * wy * a;
                    const float2* vp = (const float2*)(vbase +
                        ((size_t)l * 1024 + yi * 32 + xi) * D_);
                    float2 v = vp[lane];
                    acc.x += v.x * w;
                    acc.y += v.y * w;
                }
            }
        }
    }
    float2 o = { rnd_tf32(acc.x), rnd_tf32(acc.y) };
    ((float2*)(out + (size_t)bq * D_ + h * DH_))[lane] = o;
}

// ---------------------------------------------------------------------------
// Final residual combine: out = src3 + g1*(attn + g2*attn2)
// ---------------------------------------------------------------------------
__global__ void final_kernel(
    const float* __restrict__ src3, const float* __restrict__ attn,
    const float* __restrict__ attn2, const float* __restrict__ g1,
    const float* __restrict__ g2, float* __restrict__ out, int n4)
{
    int i = blockIdx.x * blockDim.x + threadIdx.x;
    if (i >= n4) return;
    int d4 = i & (D_ / 4 - 1);
    float4 s = ((const float4*)src3)[i];
    float4 a = ((const float4*)attn)[i];
    float4 a2 = ((const float4*)attn2)[i];
    float4 G1 = ((const float4*)g1)[d4];
    float4 G2 = ((const float4*)g2)[d4];
    float4 o;
    o.x = s.x + G1.x * (a.x + G2.x * a2.x);
    o.y = s.y + G1.y * (a.y + G2.y * a2.y);
    o.z = s.z + G1.z * (a.z + G2.z * a2.z);
    o.w = s.w + G1.w * (a.w + G2.w * a2.w);
    ((float4*)out)[i] = o;
}

// ---------------------------------------------------------------------------
// Host launcher
// ---------------------------------------------------------------------------
extern "C" void kernel_launch(void* const* d_in, const int* in_sizes, int n_in,
                              void* d_out, int out_size)
{
    const float* src[4] = {(const float*)d_in[0], (const float*)d_in[1],
                           (const float*)d_in[2], (const float*)d_in[3]};
    const float* qn_g = (const float*)d_in[4];
    const float* qn_b = (const float*)d_in[5];
    const float* fn_g = (const float*)d_in[6];
    const float* fn_b = (const float*)d_in[7];
    const float* n1_g = (const float*)d_in[8];
    const float* n1_b = (const float*)d_in[9];
    const float* gamma1 = (const float*)d_in[10];
    const float* gamma2 = (const float*)d_in[11];
    const float* ca_vb = (const float*)d_in[13];
    const float* ca_ob = (const float*)d_in[15];
    const float* ca_ab = (const float*)d_in[17];
    const float* ca_pb = (const float*)d_in[19];
    const float* sa_vb = (const float*)d_in[21];
    const float* sa_ob = (const float*)d_in[23];
    const float* sa_ab = (const float*)d_in[25];
    const float* sa_pb = (const float*)d_in[27];

    float *fn, *qn, *val, *off, *aw, *samp, *attn, *attn1;
    float *val2, *off2, *aw2, *samp2, *attn2, *wr;
    cudaGetSymbolAddress((void**)&fn,    g_fn);
    cudaGetSymbolAddress((void**)&qn,    g_qn);
    cudaGetSymbolAddress((void**)&val,   g_val);
    cudaGetSymbolAddress((void**)&off,   g_off);
    cudaGetSymbolAddress((void**)&aw,    g_aw);
    cudaGetSymbolAddress((void**)&samp,  g_samp);
    cudaGetSymbolAddress((void**)&attn,  g_attn);
    cudaGetSymbolAddress((void**)&attn1, g_attn1);
    cudaGetSymbolAddress((void**)&val2,  g_val2);
    cudaGetSymbolAddress((void**)&off2,  g_off2);
    cudaGetSymbolAddress((void**)&aw2,   g_aw2);
    cudaGetSymbolAddress((void**)&samp2, g_samp2);
    cudaGetSymbolAddress((void**)&attn2, g_attn2);
    cudaGetSymbolAddress((void**)&wr,    g_wr);

    const int ROWS = B_ * LQ_;                    // 4096
    const int SMEM = 2 * NSTAGE * STG * 4;        // 110592 bytes

    cudaFuncSetAttribute(gemm_tf32, cudaFuncAttributeMaxDynamicSharedMemorySize, SMEM);

    WPtrs wp = { (const float4*)d_in[12], (const float4*)d_in[14],
                 (const float4*)d_in[16], (const float4*)d_in[18],
                 (const float4*)d_in[20], (const float4*)d_in[22],
                 (const float4*)d_in[24], (const float4*)d_in[26] };

    // Launch order arranged so ncu (-s 5 -c 1) captures launch #6 = CA value GEMM.
    // 1-2) LayerNorms (tf32-rounded outputs)
    ln_feat_kernel<<<4 * ROWS, 256>>>(src[0], src[1], src[2], src[3], fn_g, fn_b, fn);
    ln_kernel<true><<<ROWS, 256>>>(src[3], qn_g, qn_b, qn, LQ_, LQ_, 0);
    // 3) Round weights to tf32
    round_weights<<<(WTOT / 4 + 255) / 256, 256>>>(wp, (float4*)wr);
    // 4-6) CA GEMMs (off, aw, value)
    gemm_tf32<<<dim3(4, 32),  256, SMEM>>>(qn, wr + WOFF_CAOW, ca_ob, off, 512);
    gemm_tf32<<<dim3(2, 32),  256, SMEM>>>(qn, wr + WOFF_CAAW, ca_ab, aw,  256);
    gemm_tf32<<<dim3(8, 128), 256, SMEM>>>(fn, wr + WOFF_CAVW, ca_vb, val, 1024);
    // 7-9) softmax, sample, project
    softmax_kernel<<<(ROWS * NH_ + 255) / 256, 256>>>(aw, 16, ROWS * NH_);
    deform_sample<4><<<ROWS, 512>>>(val, off, aw, samp);
    gemm_tf32<<<dim3(8, 32),  256, SMEM>>>(samp, wr + WOFF_CAPW, ca_pb, attn, 1024);
    // 10-16) SA branch
    ln_kernel<true><<<ROWS, 256>>>(attn, n1_g, n1_b, attn1, LQ_, LQ_, 0);
    gemm_tf32<<<dim3(8, 32),  256, SMEM>>>(attn1, wr + WOFF_SAVW, sa_vb, val2, 1024);
    gemm_tf32<<<dim3(1, 32),  256, SMEM>>>(attn1, wr + WOFF_SAOW, sa_ob, off2, 128);
    gemm_tf32<<<dim3(1, 32),  256, SMEM>>>(attn1, wr + WOFF_SAAW, sa_ab, aw2,  64);
    softmax_kernel<<<(ROWS * NH_ + 255) / 256, 256>>>(aw2, 4, ROWS * NH_);
    deform_sample<1><<<ROWS, 512>>>(val2, off2, aw2, samp2);
    gemm_tf32<<<dim3(8, 32),  256, SMEM>>>(samp2, wr + WOFF_SAPW, sa_pb, attn2, 1024);
    // 17) Final combine
    final_kernel<<<(ROWS * D_ / 4 + 255) / 256, 256>>>(
        src[3], attn, attn2, gamma1, gamma2, (float*)d_out, ROWS * D_ / 4);
}

// round 6
// speedup vs baseline: 1.4666x; 1.0463x over previous
#include <cuda_runtime.h>
#include <math.h>
#include <stdint.h>

// Problem constants
#define B_   4
#define E_   32
#define D_   1024
#define NH_  16
#define NP_  4
#define LQ_  1024          // E*E
#define DH_  64            // D/NH

// ---------------------------------------------------------------------------
// Scratch (static device globals; allocation APIs are forbidden)
// ---------------------------------------------------------------------------
__device__ float g_fn   [B_ * 4 * LQ_ * D_];   // 64 MB  LN(concat srcs), tf32
__device__ float g_qn   [B_ * LQ_ * D_];       // 16 MB  LN(src3), tf32
__device__ float g_val  [B_ * 4 * LQ_ * D_];   // 64 MB  CA value
__device__ float g_off  [B_ * LQ_ * 512];      //  8 MB
__device__ float g_aw   [B_ * LQ_ * 256];      //  4 MB
__device__ float g_samp [B_ * LQ_ * D_];       // 16 MB  CA sampled, tf32
__device__ float g_attn [B_ * LQ_ * D_];       // 16 MB
__device__ float g_attn1[B_ * LQ_ * D_];       // 16 MB  LN(attn), tf32
__device__ float g_val2 [B_ * LQ_ * D_];       // 16 MB
__device__ float g_off2 [B_ * LQ_ * 128];      //  2 MB
__device__ float g_aw2  [B_ * LQ_ * 64];       //  1 MB
__device__ float g_samp2[B_ * LQ_ * D_];       // 16 MB  tf32
__device__ float g_attn2[B_ * LQ_ * D_];       // 16 MB
__device__ float g_wr   [5177344];             // 20.7 MB tf32-rounded weights

// Weight segment offsets (floats) inside g_wr
#define WOFF_CAVW 0
#define WOFF_CAOW 1048576
#define WOFF_CAAW 1572864
#define WOFF_CAPW 1835008
#define WOFF_SAVW 2883584
#define WOFF_SAOW 3932160
#define WOFF_SAAW 4063232
#define WOFF_SAPW 4128768
#define WTOT      5177344

// ---------------------------------------------------------------------------
// Helpers
// ---------------------------------------------------------------------------
__device__ __forceinline__ uint32_t smem_u32(const void* p) {
    uint32_t a;
    asm("{ .reg .u64 t; cvta.to.shared.u64 t, %1; cvt.u32.u64 %0, t; }"
        : "=r"(a) : "l"(p));
    return a;
}
__device__ __forceinline__ void cp16(uint32_t s, const void* g) {
    asm volatile("cp.async.cg.shared.global [%0], [%1], 16;\n" :: "r"(s), "l"(g));
}
__device__ __forceinline__ void cp16p(uint32_t s, const void* g, uint32_t nbytes) {
    asm volatile("cp.async.cg.shared.global [%0], [%1], 16, %2;\n"
                 :: "r"(s), "l"(g), "r"(nbytes));
}
__device__ __forceinline__ float rnd_tf32(float f) {
    uint32_t o;
    asm("cvt.rna.tf32.f32 %0, %1;" : "=r"(o) : "f"(f));
    return __uint_as_float(o);
}
__device__ __forceinline__ void mma_tf32(float* d, const uint32_t* a, const uint32_t* b) {
    asm volatile(
        "mma.sync.aligned.m16n8k8.row.col.f32.tf32.tf32.f32 "
        "{%0,%1,%2,%3}, {%4,%5,%6,%7}, {%8,%9}, {%0,%1,%2,%3};"
        : "+f"(d[0]), "+f"(d[1]), "+f"(d[2]), "+f"(d[3])
        : "r"(a[0]), "r"(a[1]), "r"(a[2]), "r"(a[3]), "r"(b[0]), "r"(b[1]));
}

// ---------------------------------------------------------------------------
// TF32 tensor-core GEMM:  C(M,N) = A(M,K=1024) @ W(N,K=1024)^T + bias(N)
// Block 128x128x32, 256 threads / 8 warps (each warp 32x64), 2-stage cp.async,
// __launch_bounds__(256, 2) -> regs <= 128 -> 2 CTAs/SM (16 warps) resident.
// Inputs A/W pre-rounded to tf32 (raw bits fed to mma, no in-loop cvt).
// k-permutation: quad-lane c owns smem k-positions [8c, 8c+8); MMA step i
// consumes {8c+2i, 8c+2i+1} -> all fragment loads are LDS.64. Valid because
// A and B use the same k-bijection within each BK=32 stage.
// ---------------------------------------------------------------------------
#define LDSS 36          // smem row stride in floats (32 + 4 pad)
#define STG  (128*LDSS)  // floats per matrix per stage
#define NSTAGE 2

__global__ void __launch_bounds__(256, 2) gemm_tf32(
    const float* __restrict__ A, const float* __restrict__ W,
    const float* __restrict__ bias, float* __restrict__ C, int N)
{
    extern __shared__ float sm[];
    float* Asm = sm;
    float* Bsm = sm + NSTAGE * STG;

    const int K = 1024, NIT = 32;
    int tid = threadIdx.x, wid = tid >> 5, lane = tid & 31;
    int wm = wid & 3, wn = wid >> 2;          // warp tile: rows wm*32, cols wn*64
    int g = lane >> 2, c = lane & 3;
    int bm = blockIdx.y * 128, bn = blockIdx.x * 128;

    uint32_t abase = smem_u32(Asm), bbase = smem_u32(Bsm);

    float acc[2][8][4];
    #pragma unroll
    for (int mt = 0; mt < 2; mt++)
        #pragma unroll
        for (int nt = 0; nt < 8; nt++)
            #pragma unroll
            for (int i = 0; i < 4; i++) acc[mt][nt][i] = 0.f;

    int rowA = tid >> 3, jA = tid & 7;   // 256 threads: 32 rows x 8 chunks / pass

    auto load_stage = [&](int s, int it) {
        int k0 = it * 32;
        #pragma unroll
        for (int i = 0; i < 4; ++i) {
            int row = rowA + i * 32;
            cp16(abase + (uint32_t)(s * STG + row * LDSS + jA * 4) * 4,
                 A + (size_t)(bm + row) * K + k0 + jA * 4);
        }
        #pragma unroll
        for (int i = 0; i < 4; ++i) {
            int row = rowA + i * 32;
            int srow = bn + row;
            const float* src = W + (size_t)(srow < N ? srow : 0) * K + k0 + jA * 4;
            cp16p(bbase + (uint32_t)(s * STG + row * LDSS + jA * 4) * 4,
                  src, srow < N ? 16u : 0u);
        }
        asm volatile("cp.async.commit_group;" ::: "memory");
    };

    load_stage(0, 0);
    load_stage(1, 1);

    int s = 0;
    for (int it = 0; it < NIT; ++it) {
        asm volatile("cp.async.wait_group 1;" ::: "memory");
        __syncthreads();

        const float* Ab = Asm + s * STG;
        const float* Bb = Bsm + s * STG;
        int kc = 8 * c;
        #pragma unroll
        for (int ks = 0; ks < 4; ks++) {
            uint32_t af[2][4];
            int col = kc + 2 * ks;
            #pragma unroll
            for (int mt = 0; mt < 2; mt++) {
                int r = wm * 32 + mt * 16 + g;
                float2 a0 = *(const float2*)&Ab[r * LDSS + col];
                float2 a1 = *(const float2*)&Ab[(r + 8) * LDSS + col];
                af[mt][0] = __float_as_uint(a0.x);
                af[mt][1] = __float_as_uint(a1.x);
                af[mt][2] = __float_as_uint(a0.y);
                af[mt][3] = __float_as_uint(a1.y);
            }
            #pragma unroll
            for (int h = 0; h < 2; h++) {     // B fragments in halves: 8 regs live
                uint32_t bf[4][2];
                #pragma unroll
                for (int nt = 0; nt < 4; nt++) {
                    int r = wn * 64 + (h * 4 + nt) * 8 + g;
                    float2 b = *(const float2*)&Bb[r * LDSS + col];
                    bf[nt][0] = __float_as_uint(b.x);
                    bf[nt][1] = __float_as_uint(b.y);
                }
                #pragma unroll
                for (int mt = 0; mt < 2; mt++)
                    #pragma unroll
                    for (int nt = 0; nt < 4; nt++)
                        mma_tf32(acc[mt][h * 4 + nt], af[mt], bf[nt]);
            }
        }
        __syncthreads();
        if (it + 2 < NIT) load_stage(s, it + 2);
        s ^= 1;
    }

    // Epilogue
    #pragma unroll
    for (int mt = 0; mt < 2; mt++) {
        int r0 = bm + wm * 32 + mt * 16 + g;
        #pragma unroll
        for (int nt = 0; nt < 8; nt++) {
            int colb = bn + wn * 64 + nt * 8;
            if (colb < N) {
                int cg = colb + 2 * c;
                float2 bv = *(const float2*)(bias + cg);
                float2 o0 = { acc[mt][nt][0] + bv.x, acc[mt][nt][1] + bv.y };
                float2 o1 = { acc[mt][nt][2] + bv.x, acc[mt][nt][3] + bv.y };
                *(float2*)(C + (size_t)r0 * N + cg) = o0;
                *(float2*)(C + (size_t)(r0 + 8) * N + cg) = o1;
            }
        }
    }
}

// ---------------------------------------------------------------------------
// LayerNorm (one block per 1024-float row). RND: round output to tf32.
// ---------------------------------------------------------------------------
template<bool RND>
__global__ void __launch_bounds__(256) ln_kernel(
    const float* __restrict__ in, const float* __restrict__ g,
    const float* __restrict__ b, float* __restrict__ out,
    int in_rpb, int out_rpb, int out_off)
{
    __shared__ float red[16];
    int r = blockIdx.x;
    int bb = r / in_rpb;
    int rr = r - bb * in_rpb;
    const float4* x4 = (const float4*)(in + (size_t)r * D_);
    float4* y4 = (float4*)(out + ((size_t)bb * out_rpb + out_off + rr) * D_);

    int t = threadIdx.x;
    float4 v = x4[t];
    float s  = v.x + v.y + v.z + v.w;
    float ss = v.x * v.x + v.y * v.y + v.z * v.z + v.w * v.w;
    #pragma unroll
    for (int o = 16; o; o >>= 1) {
        s  += __shfl_xor_sync(0xFFFFFFFFu, s,  o);
        ss += __shfl_xor_sync(0xFFFFFFFFu, ss, o);
    }
    int warp = t >> 5, lane = t & 31;
    if (lane == 0) { red[warp] = s; red[8 + warp] = ss; }
    __syncthreads();
    if (t == 0) {
        float S = 0.f, SS = 0.f;
        #pragma unroll
        for (int i = 0; i < 8; i++) { S += red[i]; SS += red[8 + i]; }
        red[0] = S; red[8] = SS;
    }
    __syncthreads();
    float mean = red[0] * (1.0f / D_);
    float var  = red[8] * (1.0f / D_) - mean * mean;
    float inv  = rsqrtf(var + 1e-6f);

    float4 gg = ((const float4*)g)[t];
    float4 bv = ((const float4*)b)[t];
    float4 o;
    o.x = (v.x - mean) * inv * gg.x + bv.x;
    o.y = (v.y - mean) * inv * gg.y + bv.y;
    o.z = (v.z - mean) * inv * gg.z + bv.z;
    o.w = (v.w - mean) * inv * gg.w + bv.w;
    if (RND) {
        o.x = rnd_tf32(o.x); o.y = rnd_tf32(o.y);
        o.z = rnd_tf32(o.z); o.w = rnd_tf32(o.w);
    }
    y4[t] = o;
}

// Fused feat-LN: 4 srcs -> concat layout, tf32-rounded. grid = 16384.
__global__ void __launch_bounds__(256) ln_feat_kernel(
    const float* __restrict__ s0, const float* __restrict__ s1,
    const float* __restrict__ s2, const float* __restrict__ s3,
    const float* __restrict__ g, const float* __restrict__ b,
    float* __restrict__ out)
{
    __shared__ float red[16];
    int l = blockIdx.x >> 12;
    int r = blockIdx.x & 4095;
    const float* in = (l == 0) ? s0 : (l == 1) ? s1 : (l == 2) ? s2 : s3;
    int bb = r >> 10, rr = r & 1023;
    const float4* x4 = (const float4*)(in + (size_t)r * D_);
    float4* y4 = (float4*)(out + ((size_t)bb * 4096 + l * 1024 + rr) * D_);

    int t = threadIdx.x;
    float4 v = x4[t];
    float s  = v.x + v.y + v.z + v.w;
    float ss = v.x * v.x + v.y * v.y + v.z * v.z + v.w * v.w;
    #pragma unroll
    for (int o = 16; o; o >>= 1) {
        s  += __shfl_xor_sync(0xFFFFFFFFu, s,  o);
        ss += __shfl_xor_sync(0xFFFFFFFFu, ss, o);
    }
    int warp = t >> 5, lane = t & 31;
    if (lane == 0) { red[warp] = s; red[8 + warp] = ss; }
    __syncthreads();
    if (t == 0) {
        float S = 0.f, SS = 0.f;
        #pragma unroll
        for (int i = 0; i < 8; i++) { S += red[i]; SS += red[8 + i]; }
        red[0] = S; red[8] = SS;
    }
    __syncthreads();
    float mean = red[0] * (1.0f / D_);
    float var  = red[8] * (1.0f / D_) - mean * mean;
    float inv  = rsqrtf(var + 1e-6f);

    float4 gg = ((const float4*)g)[t];
    float4 bv = ((const float4*)b)[t];
    float4 o;
    o.x = rnd_tf32((v.x - mean) * inv * gg.x + bv.x);
    o.y = rnd_tf32((v.y - mean) * inv * gg.y + bv.y);
    o.z = rnd_tf32((v.z - mean) * inv * gg.z + bv.z);
    o.w = rnd_tf32((v.w - mean) * inv * gg.w + bv.w);
    y4[t] = o;
}

// ---------------------------------------------------------------------------
// Round all 8 weight matrices to tf32 into g_wr (single launch).
// ---------------------------------------------------------------------------
struct WPtrs { const float4 *p0,*p1,*p2,*p3,*p4,*p5,*p6,*p7; };

__global__ void round_weights(WPtrs w, float4* __restrict__ dst)
{
    int i = blockIdx.x * blockDim.x + threadIdx.x;   // float4 index
    if (i >= WTOT / 4) return;
    const float4* src; int base;
    if      (i < WOFF_CAOW/4) { src = w.p0; base = 0; }
    else if (i < WOFF_CAAW/4) { src = w.p1; base = WOFF_CAOW/4; }
    else if (i < WOFF_CAPW/4) { src = w.p2; base = WOFF_CAAW/4; }
    else if (i < WOFF_SAVW/4) { src = w.p3; base = WOFF_CAPW/4; }
    else if (i < WOFF_SAOW/4) { src = w.p4; base = WOFF_SAVW/4; }
    else if (i < WOFF_SAAW/4) { src = w.p5; base = WOFF_SAOW/4; }
    else if (i < WOFF_SAPW/4) { src = w.p6; base = WOFF_SAAW/4; }
    else                      { src = w.p7; base = WOFF_SAPW/4; }
    float4 v = src[i - base];
    v.x = rnd_tf32(v.x); v.y = rnd_tf32(v.y);
    v.z = rnd_tf32(v.z); v.w = rnd_tf32(v.w);
    dst[i] = v;
}

// ---------------------------------------------------------------------------
// Softmax over P contiguous entries per (b,q,h).
// ---------------------------------------------------------------------------
__global__ void softmax_kernel(float* __restrict__ aw, int P, int total)
{
    int i = blockIdx.x * blockDim.x + threadIdx.x;
    if (i >= total) return;
    float* p = aw + (size_t)i * P;
    float m = -1e30f;
    for (int j = 0; j < P; j++) m = fmaxf(m, p[j]);
    float s = 0.f;
    for (int j = 0; j < P; j++) { float e = __expf(p[j] - m); p[j] = e; s += e; }
    float inv = 1.0f / s;
    for (int j = 0; j < P; j++) p[j] *= inv;
}

// ---------------------------------------------------------------------------
// Deformable sampling: 1 block per (b,q), 16 warps = heads, float2 per lane.
// Output rounded to tf32 (feeds the projection GEMM).
// ---------------------------------------------------------------------------
template<int NL>
__global__ void __launch_bounds__(512) deform_sample(
    const float* __restrict__ value, const float* __restrict__ off,
    const float* __restrict__ attw, float* __restrict__ out)
{
    int bq = blockIdx.x;
    int b = bq >> 10, q = bq & 1023;
    int h = threadIdx.x >> 5, lane = threadIdx.x & 31;

    float rx = ((q & 31) + 0.5f) * 0.03125f;
    float ry = ((q >> 5) + 0.5f) * 0.03125f;

    const float* offp = off  + ((size_t)bq * NH_ + h) * (NL * NP_ * 2);
    const float* awp  = attw + ((size_t)bq * NH_ + h) * (NL * NP_);
    const float* vbase = value + (size_t)b * (NL * 1024) * D_ + h * DH_;

    float2 acc = make_float2(0.f, 0.f);

    #pragma unroll
    for (int l = 0; l < NL; l++) {
        #pragma unroll
        for (int p = 0; p < NP_; p++) {
            int s = l * NP_ + p;
            float ox = offp[s * 2 + 0];
            float oy = offp[s * 2 + 1];
            float a  = awp[s];
            float x = (rx + ox * 0.03125f) * 32.0f - 0.5f;
            float y = (ry + oy * 0.03125f) * 32.0f - 0.5f;
            float x0f = floorf(x), y0f = floorf(y);
            float wx1 = x - x0f, wy1 = y - y0f;
            int x0 = (int)x0f, y0 = (int)y0f;
            #pragma unroll
            for (int dy = 0; dy < 2; dy++) {
                int yi = y0 + dy;
                if ((unsigned)yi >= 32u) continue;
                float wy = dy ? wy1 : (1.0f - wy1);
                #pragma unroll
                for (int dx = 0; dx < 2; dx++) {
                    int xi = x0 + dx;
                    if ((unsigned)xi >= 32u) continue;
                    float w = (dx ? wx1 : (1.0f - wx1)) * wy * a;
                    const float2* vp = (const float2*)(vbase +
                        ((size_t)l * 1024 + yi * 32 + xi) * D_);
                    float2 v = vp[lane];
                    acc.x += v.x * w;
                    acc.y += v.y * w;
                }
            }
        }
    }
    float2 o = { rnd_tf32(acc.x), rnd_tf32(acc.y) };
    ((float2*)(out + (size_t)bq * D_ + h * DH_))[lane] = o;
}

// ---------------------------------------------------------------------------
// Final residual combine: out = src3 + g1*(attn + g2*attn2)
// ---------------------------------------------------------------------------
__global__ void final_kernel(
    const float* __restrict__ src3, const float* __restrict__ attn,
    const float* __restrict__ attn2, const float* __restrict__ g1,
    const float* __restrict__ g2, float* __restrict__ out, int n4)
{
    int i = blockIdx.x * blockDim.x + threadIdx.x;
    if (i >= n4) return;
    int d4 = i & (D_ / 4 - 1);
    float4 s = ((const float4*)src3)[i];
    float4 a = ((const float4*)attn)[i];
    float4 a2 = ((const float4*)attn2)[i];
    float4 G1 = ((const float4*)g1)[d4];
    float4 G2 = ((const float4*)g2)[d4];
    float4 o;
    o.x = s.x + G1.x * (a.x + G2.x * a2.x);
    o.y = s.y + G1.y * (a.y + G2.y * a2.y);
    o.z = s.z + G1.z * (a.z + G2.z * a2.z);
    o.w = s.w + G1.w * (a.w + G2.w * a2.w);
    ((float4*)out)[i] = o;
}

// ---------------------------------------------------------------------------
// Host launcher
// ---------------------------------------------------------------------------
extern "C" void kernel_launch(void* const* d_in, const int* in_sizes, int n_in,
                              void* d_out, int out_size)
{
    const float* src[4] = {(const float*)d_in[0], (const float*)d_in[1],
                           (const float*)d_in[2], (const float*)d_in[3]};
    const float* qn_g = (const float*)d_in[4];
    const float* qn_b = (const float*)d_in[5];
    const float* fn_g = (const float*)d_in[6];
    const float* fn_b = (const float*)d_in[7];
    const float* n1_g = (const float*)d_in[8];
    const float* n1_b = (const float*)d_in[9];
    const float* gamma1 = (const float*)d_in[10];
    const float* gamma2 = (const float*)d_in[11];
    const float* ca_vb = (const float*)d_in[13];
    const float* ca_ob = (const float*)d_in[15];
    const float* ca_ab = (const float*)d_in[17];
    const float* ca_pb = (const float*)d_in[19];
    const float* sa_vb = (const float*)d_in[21];
    const float* sa_ob = (const float*)d_in[23];
    const float* sa_ab = (const float*)d_in[25];
    const float* sa_pb = (const float*)d_in[27];

    float *fn, *qn, *val, *off, *aw, *samp, *attn, *attn1;
    float *val2, *off2, *aw2, *samp2, *attn2, *wr;
    cudaGetSymbolAddress((void**)&fn,    g_fn);
    cudaGetSymbolAddress((void**)&qn,    g_qn);
    cudaGetSymbolAddress((void**)&val,   g_val);
    cudaGetSymbolAddress((void**)&off,   g_off);
    cudaGetSymbolAddress((void**)&aw,    g_aw);
    cudaGetSymbolAddress((void**)&samp,  g_samp);
    cudaGetSymbolAddress((void**)&attn,  g_attn);
    cudaGetSymbolAddress((void**)&attn1, g_attn1);
    cudaGetSymbolAddress((void**)&val2,  g_val2);
    cudaGetSymbolAddress((void**)&off2,  g_off2);
    cudaGetSymbolAddress((void**)&aw2,   g_aw2);
    cudaGetSymbolAddress((void**)&samp2, g_samp2);
    cudaGetSymbolAddress((void**)&attn2, g_attn2);
    cudaGetSymbolAddress((void**)&wr,    g_wr);

    const int ROWS = B_ * LQ_;                    // 4096
    const int SMEM = 2 * NSTAGE * STG * 4;        // 73728 bytes

    cudaFuncSetAttribute(gemm_tf32, cudaFuncAttributeMaxDynamicSharedMemorySize, SMEM);

    WPtrs wp = { (const float4*)d_in[12], (const float4*)d_in[14],
                 (const float4*)d_in[16], (const float4*)d_in[18],
                 (const float4*)d_in[20], (const float4*)d_in[22],
                 (const float4*)d_in[24], (const float4*)d_in[26] };

    // 1-2) LayerNorms (tf32-rounded outputs)
    ln_feat_kernel<<<4 * ROWS, 256>>>(src[0], src[1], src[2], src[3], fn_g, fn_b, fn);
    ln_kernel<true><<<ROWS, 256>>>(src[3], qn_g, qn_b, qn, LQ_, LQ_, 0);
    // 3) Round weights to tf32
    round_weights<<<(WTOT / 4 + 255) / 256, 256>>>(wp, (float4*)wr);
    // 4-6) CA GEMMs (off, aw, value)
    gemm_tf32<<<dim3(4, 32),  256, SMEM>>>(qn, wr + WOFF_CAOW, ca_ob, off, 512);
    gemm_tf32<<<dim3(2, 32),  256, SMEM>>>(qn, wr + WOFF_CAAW, ca_ab, aw,  256);
    gemm_tf32<<<dim3(8, 128), 256, SMEM>>>(fn, wr + WOFF_CAVW, ca_vb, val, 1024);
    // 7-9) softmax, sample, project
    softmax_kernel<<<(ROWS * NH_ + 255) / 256, 256>>>(aw, 16, ROWS * NH_);
    deform_sample<4><<<ROWS, 512>>>(val, off, aw, samp);
    gemm_tf32<<<dim3(8, 32),  256, SMEM>>>(samp, wr + WOFF_CAPW, ca_pb, attn, 1024);
    // 10-16) SA branch
    ln_kernel<true><<<ROWS, 256>>>(attn, n1_g, n1_b, attn1, LQ_, LQ_, 0);
    gemm_tf32<<<dim3(8, 32),  256, SMEM>>>(attn1, wr + WOFF_SAVW, sa_vb, val2, 1024);
    gemm_tf32<<<dim3(1, 32),  256, SMEM>>>(attn1, wr + WOFF_SAOW, sa_ob, off2, 128);
    gemm_tf32<<<dim3(1, 32),  256, SMEM>>>(attn1, wr + WOFF_SAAW, sa_ab, aw2,  64);
    softmax_kernel<<<(ROWS * NH_ + 255) / 256, 256>>>(aw2, 4, ROWS * NH_);
    deform_sample<1><<<ROWS, 512>>>(val2, off2, aw2, samp2);
    gemm_tf32<<<dim3(8, 32),  256, SMEM>>>(samp2, wr + WOFF_SAPW, sa_pb, attn2, 1024);
    // 17) Final combine
    final_kernel<<<(ROWS * D_ / 4 + 255) / 256, 256>>>(
        src[3], attn, attn2, gamma1, gamma2, (float*)d_out, ROWS * D_ / 4);
}

// round 8
// speedup vs baseline: 1.4938x; 1.0185x over previous
#include <cuda_runtime.h>
#include <math.h>
#include <stdint.h>

// Problem constants
#define B_   4
#define E_   32
#define D_   1024
#define NH_  16
#define NP_  4
#define LQ_  1024          // E*E
#define DH_  64            // D/NH

// ---------------------------------------------------------------------------
// Scratch (static device globals; allocation APIs are forbidden)
// ---------------------------------------------------------------------------
__device__ float g_fn    [B_ * 4 * LQ_ * D_];   // 64 MB  LN(concat srcs), tf32
__device__ float g_qn    [B_ * LQ_ * D_];       // 16 MB  LN(src3), tf32
__device__ float g_val   [B_ * 4 * LQ_ * D_];   // 64 MB  CA value
__device__ float g_offaw [B_ * LQ_ * 768];      // 12 MB  CA off(512)+aw(256)
__device__ float g_samp  [B_ * LQ_ * D_];       // 16 MB  CA sampled, tf32
__device__ float g_attn  [B_ * LQ_ * D_];       // 16 MB
__device__ float g_attn1 [B_ * LQ_ * D_];       // 16 MB  LN(attn), tf32
__device__ float g_val2  [B_ * LQ_ * D_];       // 16 MB
__device__ float g_offaw2[B_ * LQ_ * 192];      //  3 MB  SA off(128)+aw(64)
__device__ float g_samp2 [B_ * LQ_ * D_];       // 16 MB  tf32
__device__ float g_attn2 [B_ * LQ_ * D_];       // 16 MB
__device__ float g_wr    [5177344];             // 20.7 MB tf32-rounded weights

// Weight segment offsets (floats) inside g_wr
#define WOFF_CAVW 0
#define WOFF_CAOW 1048576
#define WOFF_CAAW 1572864
#define WOFF_CAPW 1835008
#define WOFF_SAVW 2883584
#define WOFF_SAOW 3932160
#define WOFF_SAAW 4063232
#define WOFF_SAPW 4128768
#define WTOT      5177344

// ---------------------------------------------------------------------------
// Helpers
// ---------------------------------------------------------------------------
__device__ __forceinline__ uint32_t smem_u32(const void* p) {
    uint32_t a;
    asm("{ .reg .u64 t; cvta.to.shared.u64 t, %1; cvt.u32.u64 %0, t; }"
        : "=r"(a) : "l"(p));
    return a;
}
__device__ __forceinline__ void cp16(uint32_t s, const void* g) {
    asm volatile("cp.async.cg.shared.global [%0], [%1], 16;\n" :: "r"(s), "l"(g));
}
__device__ __forceinline__ void cp16p(uint32_t s, const void* g, uint32_t nbytes) {
    asm volatile("cp.async.cg.shared.global [%0], [%1], 16, %2;\n"
                 :: "r"(s), "l"(g), "r"(nbytes));
}
__device__ __forceinline__ float rnd_tf32(float f) {
    uint32_t o;
    asm("cvt.rna.tf32.f32 %0, %1;" : "=r"(o) : "f"(f));
    return __uint_as_float(o);
}
__device__ __forceinline__ void mma_tf32(float* d, const uint32_t* a, const uint32_t* b) {
    asm volatile(
        "mma.sync.aligned.m16n8k8.row.col.f32.tf32.tf32.f32 "
        "{%0,%1,%2,%3}, {%4,%5,%6,%7}, {%8,%9}, {%0,%1,%2,%3};"
        : "+f"(d[0]), "+f"(d[1]), "+f"(d[2]), "+f"(d[3])
        : "r"(a[0]), "r"(a[1]), "r"(a[2]), "r"(a[3]), "r"(b[0]), "r"(b[1]));
}

// ---------------------------------------------------------------------------
// TF32 tensor-core GEMM:  C(M,N) = A(M,K=1024) @ W(N,K=1024)^T + bias(N)
// Block 128x128x32, 256 threads / 8 warps (each warp 32x64), 2-stage cp.async.
// LDSS=36: rows 16B-aligned (cp.async 16B requires this!).
// k-bijection: within each 8-wide MMA K-group ks, thread-quad c consumes the
// physical float2 at col = 8*ks + 2*c as its (k_lo, k_hi) slots. A and B use
// the same bijection per stage, so the dot product is an exact reordering.
// Fragment banks (4g+2c) mod 32 -> uniform 2-way conflicts (vs 4-way before).
// Split-bias epilogue supports fused GEMMs: col < split -> bias1, else bias2.
// ---------------------------------------------------------------------------
#define LDSS 36          // smem row stride in floats (32 + 4 pad, 16B-aligned)
#define STG  (128*LDSS)  // floats per matrix per stage
#define NSTAGE 2

__global__ void __launch_bounds__(256, 2) gemm_tf32(
    const float* __restrict__ A, const float* __restrict__ W,
    const float* __restrict__ bias1, const float* __restrict__ bias2,
    int split, float* __restrict__ C, int N)
{
    extern __shared__ float sm[];
    float* Asm = sm;
    float* Bsm = sm + NSTAGE * STG;

    const int K = 1024, NIT = 32;
    int tid = threadIdx.x, wid = tid >> 5, lane = tid & 31;
    int wm = wid & 3, wn = wid >> 2;          // warp tile: rows wm*32, cols wn*64
    int g = lane >> 2, c = lane & 3;
    int bm = blockIdx.y * 128, bn = blockIdx.x * 128;

    uint32_t abase = smem_u32(Asm), bbase = smem_u32(Bsm);

    float acc[2][8][4];
    #pragma unroll
    for (int mt = 0; mt < 2; mt++)
        #pragma unroll
        for (int nt = 0; nt < 8; nt++)
            #pragma unroll
            for (int i = 0; i < 4; i++) acc[mt][nt][i] = 0.f;

    int rowA = tid >> 3, jA = tid & 7;   // 256 threads: 32 rows x 8 chunks / pass

    auto load_stage = [&](int s, int it) {
        int k0 = it * 32;
        #pragma unroll
        for (int i = 0; i < 4; ++i) {
            int row = rowA + i * 32;
            cp16(abase + (uint32_t)(s * STG + row * LDSS + jA * 4) * 4,
                 A + (size_t)(bm + row) * K + k0 + jA * 4);
        }
        #pragma unroll
        for (int i = 0; i < 4; ++i) {
            int row = rowA + i * 32;
            int srow = bn + row;
            const float* src = W + (size_t)(srow < N ? srow : 0) * K + k0 + jA * 4;
            cp16p(bbase + (uint32_t)(s * STG + row * LDSS + jA * 4) * 4,
                  src, srow < N ? 16u : 0u);
        }
        asm volatile("cp.async.commit_group;" ::: "memory");
    };

    load_stage(0, 0);
    load_stage(1, 1);

    int s = 0;
    for (int it = 0; it < NIT; ++it) {
        asm volatile("cp.async.wait_group 1;" ::: "memory");
        __syncthreads();

        const float* Ab = Asm + s * STG;
        const float* Bb = Bsm + s * STG;
        #pragma unroll
        for (int ks = 0; ks < 4; ks++) {
            uint32_t af[2][4];
            int col = ks * 8 + 2 * c;
            #pragma unroll
            for (int mt = 0; mt < 2; mt++) {
                int r = wm * 32 + mt * 16 + g;
                float2 a0 = *(const float2*)&Ab[r * LDSS + col];
                float2 a1 = *(const float2*)&Ab[(r + 8) * LDSS + col];
                af[mt][0] = __float_as_uint(a0.x);
                af[mt][1] = __float_as_uint(a1.x);
                af[mt][2] = __float_as_uint(a0.y);
                af[mt][3] = __float_as_uint(a1.y);
            }
            #pragma unroll
            for (int h = 0; h < 2; h++) {     // B fragments in halves: 8 regs live
                uint32_t bf[4][2];
                #pragma unroll
                for (int nt = 0; nt < 4; nt++) {
                    int r = wn * 64 + (h * 4 + nt) * 8 + g;
                    float2 b = *(const float2*)&Bb[r * LDSS + col];
                    bf[nt][0] = __float_as_uint(b.x);
                    bf[nt][1] = __float_as_uint(b.y);
                }
                #pragma unroll
                for (int mt = 0; mt < 2; mt++)
                    #pragma unroll
                    for (int nt = 0; nt < 4; nt++)
                        mma_tf32(acc[mt][h * 4 + nt], af[mt], bf[nt]);
            }
        }
        __syncthreads();
        if (it + 2 < NIT) load_stage(s, it + 2);
        s ^= 1;
    }

    // Epilogue (split-bias for fused GEMMs)
    #pragma unroll
    for (int mt = 0; mt < 2; mt++) {
        int r0 = bm + wm * 32 + mt * 16 + g;
        #pragma unroll
        for (int nt = 0; nt < 8; nt++) {
            int colb = bn + wn * 64 + nt * 8;
            if (colb < N) {
                int cg = colb + 2 * c;
                const float* bp = (colb < split) ? (bias1 + cg) : (bias2 + cg - split);
                float2 bv = *(const float2*)bp;
                float2 o0 = { acc[mt][nt][0] + bv.x, acc[mt][nt][1] + bv.y };
                float2 o1 = { acc[mt][nt][2] + bv.x, acc[mt][nt][3] + bv.y };
                *(float2*)(C + (size_t)r0 * N + cg) = o0;
                *(float2*)(C + (size_t)(r0 + 8) * N + cg) = o1;
            }
        }
    }
}

// ---------------------------------------------------------------------------
// LayerNorm (one block per 1024-float row). RND: round output to tf32.
// ---------------------------------------------------------------------------
template<bool RND>
__global__ void __launch_bounds__(256) ln_kernel(
    const float* __restrict__ in, const float* __restrict__ g,
    const float* __restrict__ b, float* __restrict__ out)
{
    __shared__ float red[16];
    int r = blockIdx.x;
    const float4* x4 = (const float4*)(in + (size_t)r * D_);
    float4* y4 = (float4*)(out + (size_t)r * D_);

    int t = threadIdx.x;
    float4 v = x4[t];
    float s  = v.x + v.y + v.z + v.w;
    float ss = v.x * v.x + v.y * v.y + v.z * v.z + v.w * v.w;
    #pragma unroll
    for (int o = 16; o; o >>= 1) {
        s  += __shfl_xor_sync(0xFFFFFFFFu, s,  o);
        ss += __shfl_xor_sync(0xFFFFFFFFu, ss, o);
    }
    int warp = t >> 5, lane = t & 31;
    if (lane == 0) { red[warp] = s; red[8 + warp] = ss; }
    __syncthreads();
    if (t == 0) {
        float S = 0.f, SS = 0.f;
        #pragma unroll
        for (int i = 0; i < 8; i++) { S += red[i]; SS += red[8 + i]; }
        red[0] = S; red[8] = SS;
    }
    __syncthreads();
    float mean = red[0] * (1.0f / D_);
    float var  = red[8] * (1.0f / D_) - mean * mean;
    float inv  = rsqrtf(var + 1e-6f);

    float4 gg = ((const float4*)g)[t];
    float4 bv = ((const float4*)b)[t];
    float4 o;
    o.x = (v.x - mean) * inv * gg.x + bv.x;
    o.y = (v.y - mean) * inv * gg.y + bv.y;
    o.z = (v.z - mean) * inv * gg.z + bv.z;
    o.w = (v.w - mean) * inv * gg.w + bv.w;
    if (RND) {
        o.x = rnd_tf32(o.x); o.y = rnd_tf32(o.y);
        o.z = rnd_tf32(o.z); o.w = rnd_tf32(o.w);
    }
    y4[t] = o;
}

// Fused feat-LN: 4 srcs -> concat layout, tf32-rounded. grid = 16384.
__global__ void __launch_bounds__(256) ln_feat_kernel(
    const float* __restrict__ s0, const float* __restrict__ s1,
    const float* __restrict__ s2, const float* __restrict__ s3,
    const float* __restrict__ g, const float* __restrict__ b,
    float* __restrict__ out)
{
    __shared__ float red[16];
    int l = blockIdx.x >> 12;
    int r = blockIdx.x & 4095;
    const float* in = (l == 0) ? s0 : (l == 1) ? s1 : (l == 2) ? s2 : s3;
    int bb = r >> 10, rr = r & 1023;
    const float4* x4 = (const float4*)(in + (size_t)r * D_);
    float4* y4 = (float4*)(out + ((size_t)bb * 4096 + l * 1024 + rr) * D_);

    int t = threadIdx.x;
    float4 v = x4[t];
    float s  = v.x + v.y + v.z + v.w;
    float ss = v.x * v.x + v.y * v.y + v.z * v.z + v.w * v.w;
    #pragma unroll
    for (int o = 16; o; o >>= 1) {
        s  += __shfl_xor_sync(0xFFFFFFFFu, s,  o);
        ss += __shfl_xor_sync(0xFFFFFFFFu, ss, o);
    }
    int warp = t >> 5, lane = t & 31;
    if (lane == 0) { red[warp] = s; red[8 + warp] = ss; }
    __syncthreads();
    if (t == 0) {
        float S = 0.f, SS = 0.f;
        #pragma unroll
        for (int i = 0; i < 8; i++) { S += red[i]; SS += red[8 + i]; }
        red[0] = S; red[8] = SS;
    }
    __syncthreads();
    float mean = red[0] * (1.0f / D_);
    float var  = red[8] * (1.0f / D_) - mean * mean;
    float inv  = rsqrtf(var + 1e-6f);

    float4 gg = ((const float4*)g)[t];
    float4 bv = ((const float4*)b)[t];
    float4 o;
    o.x = rnd_tf32((v.x - mean) * inv * gg.x + bv.x);
    o.y = rnd_tf32((v.y - mean) * inv * gg.y + bv.y);
    o.z = rnd_tf32((v.z - mean) * inv * gg.z + bv.z);
    o.w = rnd_tf32((v.w - mean) * inv * gg.w + bv.w);
    y4[t] = o;
}

// ---------------------------------------------------------------------------
// Round all 8 weight matrices to tf32 into g_wr (single launch).
// ---------------------------------------------------------------------------
struct WPtrs { const float4 *p0,*p1,*p2,*p3,*p4,*p5,*p6,*p7; };

__global__ void round_weights(WPtrs w, float4* __restrict__ dst)
{
    int i = blockIdx.x * blockDim.x + threadIdx.x;   // float4 index
    if (i >= WTOT / 4) return;
    const float4* src; int base;
    if      (i < WOFF_CAOW/4) { src = w.p0; base = 0; }
    else if (i < WOFF_CAAW/4) { src = w.p1; base = WOFF_CAOW/4; }
    else if (i < WOFF_CAPW/4) { src = w.p2; base = WOFF_CAAW/4; }
    else if (i < WOFF_SAVW/4) { src = w.p3; base = WOFF_CAPW/4; }
    else if (i < WOFF_SAOW/4) { src = w.p4; base = WOFF_SAVW/4; }
    else if (i < WOFF_SAAW/4) { src = w.p5; base = WOFF_SAOW/4; }
    else if (i < WOFF_SAPW/4) { src = w.p6; base = WOFF_SAAW/4; }
    else                      { src = w.p7; base = WOFF_SAPW/4; }
    float4 v = src[i - base];
    v.x = rnd_tf32(v.x); v.y = rnd_tf32(v.y);
    v.z = rnd_tf32(v.z); v.w = rnd_tf32(v.w);
    dst[i] = v;
}

// ---------------------------------------------------------------------------
// Softmax over P entries per (b,q,h) inside a combined off+aw row.
// Row layout: comb[bq*rstride + aoff + h*P .. +P). i = bq*16 + h.
// ---------------------------------------------------------------------------
__global__ void softmax_kernel(float* __restrict__ comb, int rstride, int aoff,
                               int P, int total)
{
    int i = blockIdx.x * blockDim.x + threadIdx.x;
    if (i >= total) return;
    float* p = comb + (size_t)(i >> 4) * rstride + aoff + (i & 15) * P;
    float m = -1e30f;
    for (int j = 0; j < P; j++) m = fmaxf(m, p[j]);
    float s = 0.f;
    for (int j = 0; j < P; j++) { float e = __expf(p[j] - m); p[j] = e; s += e; }
    float inv = 1.0f / s;
    for (int j = 0; j < P; j++) p[j] *= inv;
}

// ---------------------------------------------------------------------------
// Deformable sampling: 1 block per (b,q), 16 warps = heads, float2 per lane.
// off/aw read from combined buffer: off at bq*rstride + h*(NL*NP*2),
// aw at bq*rstride + aoff + h*(NL*NP). Output rounded to tf32.
// ---------------------------------------------------------------------------
template<int NL>
__global__ void __launch_bounds__(512) deform_sample(
    const float* __restrict__ value, const float* __restrict__ comb,
    int rstride, int aoff, float* __restrict__ out)
{
    int bq = blockIdx.x;
    int b = bq >> 10, q = bq & 1023;
    int h = threadIdx.x >> 5, lane = threadIdx.x & 31;

    float rx = ((q & 31) + 0.5f) * 0.03125f;
    float ry = ((q >> 5) + 0.5f) * 0.03125f;

    const float* offp = comb + (size_t)bq * rstride + h * (NL * NP_ * 2);
    const float* awp  = comb + (size_t)bq * rstride + aoff + h * (NL * NP_);
    const float* vbase = value + (size_t)b * (NL * 1024) * D_ + h * DH_;

    float2 acc = make_float2(0.f, 0.f);

    #pragma unroll
    for (int l = 0; l < NL; l++) {
        #pragma unroll
        for (int p = 0; p < NP_; p++) {
            int s = l * NP_ + p;
            float ox = offp[s * 2 + 0];
            float oy = offp[s * 2 + 1];
            float a  = awp[s];
            float x = (rx + ox * 0.03125f) * 32.0f - 0.5f;
            float y = (ry + oy * 0.03125f) * 32.0f - 0.5f;
            float x0f = floorf(x), y0f = floorf(y);
            float wx1 = x - x0f, wy1 = y - y0f;
            int x0 = (int)x0f, y0 = (int)y0f;
            #pragma unroll
            for (int dy = 0; dy < 2; dy++) {
                int yi = y0 + dy;
                if ((unsigned)yi >= 32u) continue;
                float wy = dy ? wy1 : (1.0f - wy1);
                #pragma unroll
                for (int dx = 0; dx < 2; dx++) {
                    int xi = x0 + dx;
                    if ((unsigned)xi >= 32u) continue;
                    float w = (dx ? wx1 : (1.0f - wx1)) * wy * a;
                    const float2* vp = (const float2*)(vbase +
                        ((size_t)l * 1024 + yi * 32 + xi) * D_);
                    float2 v = vp[lane];
                    acc.x += v.x * w;
                    acc.y += v.y * w;
                }
            }
        }
    }
    float2 o = { rnd_tf32(acc.x), rnd_tf32(acc.y) };
    ((float2*)(out + (size_t)bq * D_ + h * DH_))[lane] = o;
}

// ---------------------------------------------------------------------------
// Final residual combine: out = src3 + g1*(attn + g2*attn2)
// ---------------------------------------------------------------------------
__global__ void final_kernel(
    const float* __restrict__ src3, const float* __restrict__ attn,
    const float* __restrict__ attn2, const float* __restrict__ g1,
    const float* __restrict__ g2, float* __restrict__ out, int n4)
{
    int i = blockIdx.x * blockDim.x + threadIdx.x;
    if (i >= n4) return;
    int d4 = i & (D_ / 4 - 1);
    float4 s = ((const float4*)src3)[i];
    float4 a = ((const float4*)attn)[i];
    float4 a2 = ((const float4*)attn2)[i];
    float4 G1 = ((const float4*)g1)[d4];
    float4 G2 = ((const float4*)g2)[d4];
    float4 o;
    o.x = s.x + G1.x * (a.x + G2.x * a2.x);
    o.y = s.y + G1.y * (a.y + G2.y * a2.y);
    o.z = s.z + G1.z * (a.z + G2.z * a2.z);
    o.w = s.w + G1.w * (a.w + G2.w * a2.w);
    ((float4*)out)[i] = o;
}

// ---------------------------------------------------------------------------
// Host launcher
// ---------------------------------------------------------------------------
extern "C" void kernel_launch(void* const* d_in, const int* in_sizes, int n_in,
                              void* d_out, int out_size)
{
    const float* src[4] = {(const float*)d_in[0], (const float*)d_in[1],
                           (const float*)d_in[2], (const float*)d_in[3]};
    const float* qn_g = (const float*)d_in[4];
    const float* qn_b = (const float*)d_in[5];
    const float* fn_g = (const float*)d_in[6];
    const float* fn_b = (const float*)d_in[7];
    const float* n1_g = (const float*)d_in[8];
    const float* n1_b = (const float*)d_in[9];
    const float* gamma1 = (const float*)d_in[10];
    const float* gamma2 = (const float*)d_in[11];
    const float* ca_vb = (const float*)d_in[13];
    const float* ca_ob = (const float*)d_in[15];
    const float* ca_ab = (const float*)d_in[17];
    const float* ca_pb = (const float*)d_in[19];
    const float* sa_vb = (const float*)d_in[21];
    const float* sa_ob = (const float*)d_in[23];
    const float* sa_ab = (const float*)d_in[25];
    const float* sa_pb = (const float*)d_in[27];

    float *fn, *qn, *val, *offaw, *samp, *attn, *attn1;
    float *val2, *offaw2, *samp2, *attn2, *wr;
    cudaGetSymbolAddress((void**)&fn,     g_fn);
    cudaGetSymbolAddress((void**)&qn,     g_qn);
    cudaGetSymbolAddress((void**)&val,    g_val);
    cudaGetSymbolAddress((void**)&offaw,  g_offaw);
    cudaGetSymbolAddress((void**)&samp,   g_samp);
    cudaGetSymbolAddress((void**)&attn,   g_attn);
    cudaGetSymbolAddress((void**)&attn1,  g_attn1);
    cudaGetSymbolAddress((void**)&val2,   g_val2);
    cudaGetSymbolAddress((void**)&offaw2, g_offaw2);
    cudaGetSymbolAddress((void**)&samp2,  g_samp2);
    cudaGetSymbolAddress((void**)&attn2,  g_attn2);
    cudaGetSymbolAddress((void**)&wr,     g_wr);

    const int ROWS = B_ * LQ_;                    // 4096
    const int SMEM = 2 * NSTAGE * STG * 4;        // 73728 bytes

    cudaFuncSetAttribute(gemm_tf32, cudaFuncAttributeMaxDynamicSharedMemorySize, SMEM);

    WPtrs wp = { (const float4*)d_in[12], (const float4*)d_in[14],
                 (const float4*)d_in[16], (const float4*)d_in[18],
                 (const float4*)d_in[20], (const float4*)d_in[22],
                 (const float4*)d_in[24], (const float4*)d_in[26] };

    // 1-3) LayerNorms + weight rounding
    ln_feat_kernel<<<4 * ROWS, 256>>>(src[0], src[1], src[2], src[3], fn_g, fn_b, fn);
    ln_kernel<true><<<ROWS, 256>>>(src[3], qn_g, qn_b, qn);
    round_weights<<<(WTOT / 4 + 255) / 256, 256>>>(wp, (float4*)wr);
    // 4) Fused CA off+aw GEMM (N=768, split 512)
    gemm_tf32<<<dim3(6, 32), 256, SMEM>>>(qn, wr + WOFF_CAOW, ca_ob, ca_ab, 512, offaw, 768);
    // 5) softmax on aw part (only needs offaw)
    softmax_kernel<<<(ROWS * NH_ + 255) / 256, 256>>>(offaw, 768, 512, 16, ROWS * NH_);
    // 6) CA value GEMM (the launch ncu -s 5 -c 1 captures)
    gemm_tf32<<<dim3(8, 128), 256, SMEM>>>(fn, wr + WOFF_CAVW, ca_vb, ca_vb, 1024, val, 1024);
    // 7-8) sample + project
    deform_sample<4><<<ROWS, 512>>>(val, offaw, 768, 512, samp);
    gemm_tf32<<<dim3(8, 32), 256, SMEM>>>(samp, wr + WOFF_CAPW, ca_pb, ca_pb, 1024, attn, 1024);
    // 9-14) SA branch
    ln_kernel<true><<<ROWS, 256>>>(attn, n1_g, n1_b, attn1);
    gemm_tf32<<<dim3(8, 32), 256, SMEM>>>(attn1, wr + WOFF_SAVW, sa_vb, sa_vb, 1024, val2, 1024);
    gemm_tf32<<<dim3(2, 32), 256, SMEM>>>(attn1, wr + WOFF_SAOW, sa_ob, sa_ab, 128, offaw2, 192);
    softmax_kernel<<<(ROWS * NH_ + 255) / 256, 256>>>(offaw2, 192, 128, 4, ROWS * NH_);
    deform_sample<1><<<ROWS, 512>>>(val2, offaw2, 192, 128, samp2);
    gemm_tf32<<<dim3(8, 32), 256, SMEM>>>(samp2, wr + WOFF_SAPW, sa_pb, sa_pb, 1024, attn2, 1024);
    // 15) Final combine
    final_kernel<<<(ROWS * D_ / 4 + 255) / 256, 256>>>(
        src[3], attn, attn2, gamma1, gamma2, (float*)d_out, ROWS * D_ / 4);
}

// round 9
// speedup vs baseline: 2.5636x; 1.7162x over previous
#include <cuda_runtime.h>
#include <cuda_bf16.h>
#include <math.h>
#include <stdint.h>

typedef __nv_bfloat16 bf16;

// Problem constants
#define B_   4
#define E_   32
#define D_   1024
#define NH_  16
#define NP_  4
#define LQ_  1024          // E*E
#define DH_  64            // D/NH

// ---------------------------------------------------------------------------
// Scratch (static device globals; allocation APIs are forbidden)
// ---------------------------------------------------------------------------
__device__ bf16  g_fn    [B_ * 4 * LQ_ * D_];   // 32 MB  LN(concat srcs), bf16
__device__ bf16  g_qn    [B_ * LQ_ * D_];       //  8 MB  LN(src3), bf16
__device__ float g_val   [B_ * 4 * LQ_ * D_];   // 64 MB  CA value (fp32)
__device__ float g_offaw [B_ * LQ_ * 768];      // 12 MB  CA off(512)+aw(256)
__device__ bf16  g_samp  [B_ * LQ_ * D_];       //  8 MB  CA sampled, bf16
__device__ float g_attn  [B_ * LQ_ * D_];       // 16 MB
__device__ bf16  g_attn1 [B_ * LQ_ * D_];       //  8 MB  LN(attn), bf16
__device__ float g_val2  [B_ * LQ_ * D_];       // 16 MB
__device__ float g_offaw2[B_ * LQ_ * 192];      //  3 MB  SA off(128)+aw(64)
__device__ bf16  g_samp2 [B_ * LQ_ * D_];       //  8 MB  bf16
__device__ float g_attn2 [B_ * LQ_ * D_];       // 16 MB
__device__ bf16  g_wrb   [5177344];             // 10.4 MB bf16 weights

// Weight segment offsets (elements) inside g_wrb
#define WOFF_CAVW 0
#define WOFF_CAOW 1048576
#define WOFF_CAAW 1572864
#define WOFF_CAPW 1835008
#define WOFF_SAVW 2883584
#define WOFF_SAOW 3932160
#define WOFF_SAAW 4063232
#define WOFF_SAPW 4128768
#define WTOT      5177344

// ---------------------------------------------------------------------------
// Helpers
// ---------------------------------------------------------------------------
__device__ __forceinline__ uint32_t smem_u32(const void* p) {
    uint32_t a;
    asm("{ .reg .u64 t; cvta.to.shared.u64 t, %1; cvt.u32.u64 %0, t; }"
        : "=r"(a) : "l"(p));
    return a;
}
__device__ __forceinline__ void cp16(uint32_t s, const void* g) {
    asm volatile("cp.async.cg.shared.global [%0], [%1], 16;\n" :: "r"(s), "l"(g));
}
__device__ __forceinline__ void cp16p(uint32_t s, const void* g, uint32_t nbytes) {
    asm volatile("cp.async.cg.shared.global [%0], [%1], 16, %2;\n"
                 :: "r"(s), "l"(g), "r"(nbytes));
}
__device__ __forceinline__ void ldsm4(uint32_t* r, uint32_t a) {
    asm volatile("ldmatrix.sync.aligned.m8n8.x4.shared.b16 {%0,%1,%2,%3}, [%4];"
                 : "=r"(r[0]), "=r"(r[1]), "=r"(r[2]), "=r"(r[3]) : "r"(a));
}
__device__ __forceinline__ void mma_bf16(float* d, const uint32_t* a,
                                         uint32_t b0, uint32_t b1) {
    asm volatile(
        "mma.sync.aligned.m16n8k16.row.col.f32.bf16.bf16.f32 "
        "{%0,%1,%2,%3}, {%4,%5,%6,%7}, {%8,%9}, {%0,%1,%2,%3};"
        : "+f"(d[0]), "+f"(d[1]), "+f"(d[2]), "+f"(d[3])
        : "r"(a[0]), "r"(a[1]), "r"(a[2]), "r"(a[3]), "r"(b0), "r"(b1));
}
__device__ __forceinline__ uint32_t pack_bf16(float lo, float hi) {
    __nv_bfloat162 p = __floats2bfloat162_rn(lo, hi);
    return *reinterpret_cast<uint32_t*>(&p);
}

// ---------------------------------------------------------------------------
// BF16 tensor-core GEMM:  C(M,N) = A(M,K=1024) @ W(N,K=1024)^T + bias(N)
// Block 128x128x32, 256 threads / 8 warps (each warp 32x64), 3-stage cp.async.
// A/W are bf16 (pre-rounded by producers); C is fp32.
// Fragments via ldmatrix.x4 (no .trans needed for this NT layout).
// Smem row stride 80B (64B data + 16B pad): cp.async 16B-aligned, and the
// 8 row-addresses per ldmatrix tile hit distinct 16B bank groups.
// Split-bias epilogue supports fused GEMMs: col < split -> bias1, else bias2.
// ---------------------------------------------------------------------------
#define RSTR 80              // bytes per smem row
#define STGB (128 * RSTR)    // bytes per matrix per stage (10240)
#define NSTAGE 3

__global__ void __launch_bounds__(256, 2) gemm_bf16(
    const bf16* __restrict__ A, const bf16* __restrict__ W,
    const float* __restrict__ bias1, const float* __restrict__ bias2,
    int split, float* __restrict__ C, int N)
{
    extern __shared__ char smraw[];
    uint32_t abase = smem_u32(smraw);
    uint32_t bbase = abase + NSTAGE * STGB;

    const int K = 1024, NIT = 32;
    int tid = threadIdx.x, wid = tid >> 5, lane = tid & 31;
    int wm = wid & 3, wn = wid >> 2;          // warp tile: rows wm*32, cols wn*64
    int bm = blockIdx.y * 128, bn = blockIdx.x * 128;

    float acc[2][8][4];
    #pragma unroll
    for (int mt = 0; mt < 2; mt++)
        #pragma unroll
        for (int nt = 0; nt < 8; nt++)
            #pragma unroll
            for (int i = 0; i < 4; i++) acc[mt][nt][i] = 0.f;

    int rowC = tid >> 2, jc = tid & 3;   // 256 threads: 64 rows x 4 chunks / pass

    auto load_stage = [&](int s, int it) {
        int k0 = it * 32;                // bf16 element offset in K
        #pragma unroll
        for (int i = 0; i < 2; ++i) {
            int row = rowC + i * 64;
            cp16(abase + s * STGB + row * RSTR + jc * 16,
                 A + (size_t)(bm + row) * K + k0 + jc * 8);
            int srow = bn + row;
            const bf16* src = W + (size_t)(srow < N ? srow : 0) * K + k0 + jc * 8;
            cp16p(bbase + s * STGB + row * RSTR + jc * 16,
                  src, srow < N ? 16u : 0u);
        }
        asm volatile("cp.async.commit_group;" ::: "memory");
    };

    // Per-thread ldmatrix row addresses.
    // A x4 tiles: [rows0-7 k0-7][rows8-15 k0-7][rows0-7 k8-15][rows8-15 k8-15]
    int rA = lane & 15, hA = lane >> 4;
    uint32_t aAddr = abase + (uint32_t)(wm * 32 + rA) * RSTR + hA * 16;
    // B x4 tiles: [n0-7 k0-7][n0-7 k8-15][n8-15 k0-7][n8-15 k8-15]
    int rB = (lane & 7) | ((lane >> 4) << 3);
    int hB = (lane >> 3) & 1;
    uint32_t bAddr = bbase + (uint32_t)(wn * 64 + rB) * RSTR + hB * 16;

    load_stage(0, 0);
    load_stage(1, 1);

    int s = 0, pf = 2;
    for (int it = 0; it < NIT; ++it) {
        asm volatile("cp.async.wait_group 1;" ::: "memory");
        __syncthreads();
        if (it + 2 < NIT) {
            load_stage(pf, it + 2);
            pf = (pf == NSTAGE - 1) ? 0 : pf + 1;
        }

        uint32_t ao = aAddr + s * STGB;
        uint32_t bo = bAddr + s * STGB;
        #pragma unroll
        for (int ks = 0; ks < 2; ks++) {          // two k16 steps per BK=32
            uint32_t af[2][4];
            #pragma unroll
            for (int mt = 0; mt < 2; mt++)
                ldsm4(af[mt], ao + mt * (16 * RSTR) + ks * 32);
            #pragma unroll
            for (int nb = 0; nb < 4; nb++) {
                uint32_t bb4[4];
                ldsm4(bb4, bo + nb * (16 * RSTR) + ks * 32);
                #pragma unroll
                for (int mt = 0; mt < 2; mt++) {
                    mma_bf16(acc[mt][2 * nb],     af[mt], bb4[0], bb4[1]);
                    mma_bf16(acc[mt][2 * nb + 1], af[mt], bb4[2], bb4[3]);
                }
            }
        }
        s = (s == NSTAGE - 1) ? 0 : s + 1;
    }

    // Epilogue (split-bias for fused GEMMs)
    int g = lane >> 2, c = lane & 3;
    #pragma unroll
    for (int mt = 0; mt < 2; mt++) {
        int r0 = bm + wm * 32 + mt * 16 + g;
        #pragma unroll
        for (int nt = 0; nt < 8; nt++) {
            int colb = bn + wn * 64 + nt * 8;
            if (colb < N) {
                int cg = colb + 2 * c;
                const float* bp = (colb < split) ? (bias1 + cg) : (bias2 + cg - split);
                float2 bv = *(const float2*)bp;
                float2 o0 = { acc[mt][nt][0] + bv.x, acc[mt][nt][1] + bv.y };
                float2 o1 = { acc[mt][nt][2] + bv.x, acc[mt][nt][3] + bv.y };
                *(float2*)(C + (size_t)r0 * N + cg) = o0;
                *(float2*)(C + (size_t)(r0 + 8) * N + cg) = o1;
            }
        }
    }
}

// ---------------------------------------------------------------------------
// LayerNorm (one block per 1024-float row). fp32 in -> bf16 out.
// ---------------------------------------------------------------------------
__global__ void __launch_bounds__(256) ln_kernel(
    const float* __restrict__ in, const float* __restrict__ g,
    const float* __restrict__ b, bf16* __restrict__ out)
{
    __shared__ float red[16];
    int r = blockIdx.x;
    const float4* x4 = (const float4*)(in + (size_t)r * D_);

    int t = threadIdx.x;
    float4 v = x4[t];
    float s  = v.x + v.y + v.z + v.w;
    float ss = v.x * v.x + v.y * v.y + v.z * v.z + v.w * v.w;
    #pragma unroll
    for (int o = 16; o; o >>= 1) {
        s  += __shfl_xor_sync(0xFFFFFFFFu, s,  o);
        ss += __shfl_xor_sync(0xFFFFFFFFu, ss, o);
    }
    int warp = t >> 5, lane = t & 31;
    if (lane == 0) { red[warp] = s; red[8 + warp] = ss; }
    __syncthreads();
    if (t == 0) {
        float S = 0.f, SS = 0.f;
        #pragma unroll
        for (int i = 0; i < 8; i++) { S += red[i]; SS += red[8 + i]; }
        red[0] = S; red[8] = SS;
    }
    __syncthreads();
    float mean = red[0] * (1.0f / D_);
    float var  = red[8] * (1.0f / D_) - mean * mean;
    float inv  = rsqrtf(var + 1e-6f);

    float4 gg = ((const float4*)g)[t];
    float4 bv = ((const float4*)b)[t];
    uint2 u;
    u.x = pack_bf16((v.x - mean) * inv * gg.x + bv.x,
                    (v.y - mean) * inv * gg.y + bv.y);
    u.y = pack_bf16((v.z - mean) * inv * gg.z + bv.z,
                    (v.w - mean) * inv * gg.w + bv.w);
    ((uint2*)(out + (size_t)r * D_))[t] = u;
}

// Fused feat-LN: 4 srcs -> concat layout, bf16. grid = 16384.
__global__ void __launch_bounds__(256) ln_feat_kernel(
    const float* __restrict__ s0, const float* __restrict__ s1,
    const float* __restrict__ s2, const float* __restrict__ s3,
    const float* __restrict__ g, const float* __restrict__ b,
    bf16* __restrict__ out)
{
    __shared__ float red[16];
    int l = blockIdx.x >> 12;
    int r = blockIdx.x & 4095;
    const float* in = (l == 0) ? s0 : (l == 1) ? s1 : (l == 2) ? s2 : s3;
    int bb = r >> 10, rr = r & 1023;
    const float4* x4 = (const float4*)(in + (size_t)r * D_);
    bf16* orow = out + ((size_t)bb * 4096 + l * 1024 + rr) * D_;

    int t = threadIdx.x;
    float4 v = x4[t];
    float s  = v.x + v.y + v.z + v.w;
    float ss = v.x * v.x + v.y * v.y + v.z * v.z + v.w * v.w;
    #pragma unroll
    for (int o = 16; o; o >>= 1) {
        s  += __shfl_xor_sync(0xFFFFFFFFu, s,  o);
        ss += __shfl_xor_sync(0xFFFFFFFFu, ss, o);
    }
    int warp = t >> 5, lane = t & 31;
    if (lane == 0) { red[warp] = s; red[8 + warp] = ss; }
    __syncthreads();
    if (t == 0) {
        float S = 0.f, SS = 0.f;
        #pragma unroll
        for (int i = 0; i < 8; i++) { S += red[i]; SS += red[8 + i]; }
        red[0] = S; red[8] = SS;
    }
    __syncthreads();
    float mean = red[0] * (1.0f / D_);
    float var  = red[8] * (1.0f / D_) - mean * mean;
    float inv  = rsqrtf(var + 1e-6f);

    float4 gg = ((const float4*)g)[t];
    float4 bv = ((const float4*)b)[t];
    uint2 u;
    u.x = pack_bf16((v.x - mean) * inv * gg.x + bv.x,
                    (v.y - mean) * inv * gg.y + bv.y);
    u.y = pack_bf16((v.z - mean) * inv * gg.z + bv.z,
                    (v.w - mean) * inv * gg.w + bv.w);
    ((uint2*)orow)[t] = u;
}

// ---------------------------------------------------------------------------
// Convert all 8 weight matrices to bf16 into g_wrb (single launch).
// ---------------------------------------------------------------------------
struct WPtrs { const float4 *p0,*p1,*p2,*p3,*p4,*p5,*p6,*p7; };

__global__ void round_weights(WPtrs w, bf16* __restrict__ dst)
{
    int i = blockIdx.x * blockDim.x + threadIdx.x;   // float4 index
    if (i >= WTOT / 4) return;
    const float4* src; int base;
    if      (i < WOFF_CAOW/4) { src = w.p0; base = 0; }
    else if (i < WOFF_CAAW/4) { src = w.p1; base = WOFF_CAOW/4; }
    else if (i < WOFF_CAPW/4) { src = w.p2; base = WOFF_CAAW/4; }
    else if (i < WOFF_SAVW/4) { src = w.p3; base = WOFF_CAPW/4; }
    else if (i < WOFF_SAOW/4) { src = w.p4; base = WOFF_SAVW/4; }
    else if (i < WOFF_SAAW/4) { src = w.p5; base = WOFF_SAOW/4; }
    else if (i < WOFF_SAPW/4) { src = w.p6; base = WOFF_SAAW/4; }
    else                      { src = w.p7; base = WOFF_SAPW/4; }
    float4 v = src[i - base];
    uint2 u;
    u.x = pack_bf16(v.x, v.y);
    u.y = pack_bf16(v.z, v.w);
    ((uint2*)dst)[i] = u;
}

// ---------------------------------------------------------------------------
// Softmax over P entries per (b,q,h) inside a combined off+aw row.
// ---------------------------------------------------------------------------
__global__ void softmax_kernel(float* __restrict__ comb, int rstride, int aoff,
                               int P, int total)
{
    int i = blockIdx.x * blockDim.x + threadIdx.x;
    if (i >= total) return;
    float* p = comb + (size_t)(i >> 4) * rstride + aoff + (i & 15) * P;
    float m = -1e30f;
    for (int j = 0; j < P; j++) m = fmaxf(m, p[j]);
    float s = 0.f;
    for (int j = 0; j < P; j++) { float e = __expf(p[j] - m); p[j] = e; s += e; }
    float inv = 1.0f / s;
    for (int j = 0; j < P; j++) p[j] *= inv;
}

// ---------------------------------------------------------------------------
// Deformable sampling: 1 block per (b,q), 16 warps = heads, float2 per lane.
// Output bf16 (feeds the projection GEMM).
// ---------------------------------------------------------------------------
template<int NL>
__global__ void __launch_bounds__(512) deform_sample(
    const float* __restrict__ value, const float* __restrict__ comb,
    int rstride, int aoff, bf16* __restrict__ out)
{
    int bq = blockIdx.x;
    int b = bq >> 10, q = bq & 1023;
    int h = threadIdx.x >> 5, lane = threadIdx.x & 31;

    float rx = ((q & 31) + 0.5f) * 0.03125f;
    float ry = ((q >> 5) + 0.5f) * 0.03125f;

    const float* offp = comb + (size_t)bq * rstride + h * (NL * NP_ * 2);
    const float* awp  = comb + (size_t)bq * rstride + aoff + h * (NL * NP_);
    const float* vbase = value + (size_t)b * (NL * 1024) * D_ + h * DH_;

    float2 acc = make_float2(0.f, 0.f);

    #pragma unroll
    for (int l = 0; l < NL; l++) {
        #pragma unroll
        for (int p = 0; p < NP_; p++) {
            int s = l * NP_ + p;
            float ox = offp[s * 2 + 0];
            float oy = offp[s * 2 + 1];
            float a  = awp[s];
            float x = (rx + ox * 0.03125f) * 32.0f - 0.5f;
            float y = (ry + oy * 0.03125f) * 32.0f - 0.5f;
            float x0f = floorf(x), y0f = floorf(y);
            float wx1 = x - x0f, wy1 = y - y0f;
            int x0 = (int)x0f, y0 = (int)y0f;
            #pragma unroll
            for (int dy = 0; dy < 2; dy++) {
                int yi = y0 + dy;
                if ((unsigned)yi >= 32u) continue;
                float wy = dy ? wy1 : (1.0f - wy1);
                #pragma unroll
                for (int dx = 0; dx < 2; dx++) {
                    int xi = x0 + dx;
                    if ((unsigned)xi >= 32u) continue;
                    float w = (dx ? wx1 : (1.0f - wx1)) * wy * a;
                    const float2* vp = (const float2*)(vbase +
                        ((size_t)l * 1024 + yi * 32 + xi) * D_);
                    float2 v = vp[lane];
                    acc.x += v.x * w;
                    acc.y += v.y * w;
                }
            }
        }
    }
    uint32_t pv = pack_bf16(acc.x, acc.y);
    ((uint32_t*)(out + (size_t)bq * D_ + h * DH_))[lane] = pv;
}

// ---------------------------------------------------------------------------
// Final residual combine: out = src3 + g1*(attn + g2*attn2)
// ---------------------------------------------------------------------------
__global__ void final_kernel(
    const float* __restrict__ src3, const float* __restrict__ attn,
    const float* __restrict__ attn2, const float* __restrict__ g1,
    const float* __restrict__ g2, float* __restrict__ out, int n4)
{
    int i = blockIdx.x * blockDim.x + threadIdx.x;
    if (i >= n4) return;
    int d4 = i & (D_ / 4 - 1);
    float4 s = ((const float4*)src3)[i];
    float4 a = ((const float4*)attn)[i];
    float4 a2 = ((const float4*)attn2)[i];
    float4 G1 = ((const float4*)g1)[d4];
    float4 G2 = ((const float4*)g2)[d4];
    float4 o;
    o.x = s.x + G1.x * (a.x + G2.x * a2.x);
    o.y = s.y + G1.y * (a.y + G2.y * a2.y);
    o.z = s.z + G1.z * (a.z + G2.z * a2.z);
    o.w = s.w + G1.w * (a.w + G2.w * a2.w);
    ((float4*)out)[i] = o;
}

// ---------------------------------------------------------------------------
// Host launcher
// ---------------------------------------------------------------------------
extern "C" void kernel_launch(void* const* d_in, const int* in_sizes, int n_in,
                              void* d_out, int out_size)
{
    const float* src[4] = {(const float*)d_in[0], (const float*)d_in[1],
                           (const float*)d_in[2], (const float*)d_in[3]};
    const float* qn_g = (const float*)d_in[4];
    const float* qn_b = (const float*)d_in[5];
    const float* fn_g = (const float*)d_in[6];
    const float* fn_b = (const float*)d_in[7];
    const float* n1_g = (const float*)d_in[8];
    const float* n1_b = (const float*)d_in[9];
    const float* gamma1 = (const float*)d_in[10];
    const float* gamma2 = (const float*)d_in[11];
    const float* ca_vb = (const float*)d_in[13];
    const float* ca_ob = (const float*)d_in[15];
    const float* ca_ab = (const float*)d_in[17];
    const float* ca_pb = (const float*)d_in[19];
    const float* sa_vb = (const float*)d_in[21];
    const float* sa_ob = (const float*)d_in[23];
    const float* sa_ab = (const float*)d_in[25];
    const float* sa_pb = (const float*)d_in[27];

    bf16 *fn, *qn, *samp, *attn1, *samp2, *wr;
    float *val, *offaw, *attn, *val2, *offaw2, *attn2;
    cudaGetSymbolAddress((void**)&fn,     g_fn);
    cudaGetSymbolAddress((void**)&qn,     g_qn);
    cudaGetSymbolAddress((void**)&val,    g_val);
    cudaGetSymbolAddress((void**)&offaw,  g_offaw);
    cudaGetSymbolAddress((void**)&samp,   g_samp);
    cudaGetSymbolAddress((void**)&attn,   g_attn);
    cudaGetSymbolAddress((void**)&attn1,  g_attn1);
    cudaGetSymbolAddress((void**)&val2,   g_val2);
    cudaGetSymbolAddress((void**)&offaw2, g_offaw2);
    cudaGetSymbolAddress((void**)&samp2,  g_samp2);
    cudaGetSymbolAddress((void**)&attn2,  g_attn2);
    cudaGetSymbolAddress((void**)&wr,     g_wrb);

    const int ROWS = B_ * LQ_;                    // 4096
    const int SMEM = 2 * NSTAGE * STGB;           // 61440 bytes

    cudaFuncSetAttribute(gemm_bf16, cudaFuncAttributeMaxDynamicSharedMemorySize, SMEM);

    WPtrs wp = { (const float4*)d_in[12], (const float4*)d_in[14],
                 (const float4*)d_in[16], (const float4*)d_in[18],
                 (const float4*)d_in[20], (const float4*)d_in[22],
                 (const float4*)d_in[24], (const float4*)d_in[26] };

    // 1-3) LayerNorms + weight conversion (all bf16 outputs)
    ln_feat_kernel<<<4 * ROWS, 256>>>(src[0], src[1], src[2], src[3], fn_g, fn_b, fn);
    ln_kernel<<<ROWS, 256>>>(src[3], qn_g, qn_b, qn);
    round_weights<<<(WTOT / 4 + 255) / 256, 256>>>(wp, wr);
    // 4) Fused CA off+aw GEMM (N=768, split 512)
    gemm_bf16<<<dim3(6, 32), 256, SMEM>>>(qn, wr + WOFF_CAOW, ca_ob, ca_ab, 512, offaw, 768);
    // 5) softmax on aw part
    softmax_kernel<<<(ROWS * NH_ + 255) / 256, 256>>>(offaw, 768, 512, 16, ROWS * NH_);
    // 6) CA value GEMM (the launch ncu -s 5 -c 1 captures)
    gemm_bf16<<<dim3(8, 128), 256, SMEM>>>(fn, wr + WOFF_CAVW, ca_vb, ca_vb, 1024, val, 1024);
    // 7-8) sample + project
    deform_sample<4><<<ROWS, 512>>>(val, offaw, 768, 512, samp);
    gemm_bf16<<<dim3(8, 32), 256, SMEM>>>(samp, wr + WOFF_CAPW, ca_pb, ca_pb, 1024, attn, 1024);
    // 9-14) SA branch
    ln_kernel<<<ROWS, 256>>>(attn, n1_g, n1_b, attn1);
    gemm_bf16<<<dim3(8, 32), 256, SMEM>>>(attn1, wr + WOFF_SAVW, sa_vb, sa_vb, 1024, val2, 1024);
    gemm_bf16<<<dim3(2, 32), 256, SMEM>>>(attn1, wr + WOFF_SAOW, sa_ob, sa_ab, 128, offaw2, 192);
    softmax_kernel<<<(ROWS * NH_ + 255) / 256, 256>>>(offaw2, 192, 128, 4, ROWS * NH_);
    deform_sample<1><<<ROWS, 512>>>(val2, offaw2, 192, 128, samp2);
    gemm_bf16<<<dim3(8, 32), 256, SMEM>>>(samp2, wr + WOFF_SAPW, sa_pb, sa_pb, 1024, attn2, 1024);
    // 15) Final combine
    final_kernel<<<(ROWS * D_ / 4 + 255) / 256, 256>>>(
        src[3], attn, attn2, gamma1, gamma2, (float*)d_out, ROWS * D_ / 4);
}